// round 1
// baseline (speedup 1.0000x reference)
#include <cuda_runtime.h>

#define NN 100000
#define EE 1600000
#define HH 128
#define CC 40
#define LLAYERS 4
#define BN_EPS 1e-5f

// ---------------- scratch (device globals; no allocation allowed) ----------
__device__ float g_h[NN * HH];     // current activations
__device__ float g_tmp[NN * HH];   // pre-BN layer output
__device__ float g_agg[NN * HH];   // mean-aggregated neighbors
__device__ int   g_deg[NN];
__device__ int   g_rowptr[NN + 1];
__device__ int   g_cursor[NN];
__device__ int   g_csrc[EE];
__device__ int   g_blocksum[256];
__device__ int   g_blockoff[256];
__device__ float g_sum[HH];
__device__ float g_sumsq[HH];
__device__ float g_scale[HH];
__device__ float g_shift[HH];

// ---------------- CSR build ------------------------------------------------
__global__ void k_zero_deg() {
    int n = blockIdx.x * blockDim.x + threadIdx.x;
    if (n < NN) g_deg[n] = 0;
}

__global__ void k_hist(const int* __restrict__ ei) {
    int e = blockIdx.x * blockDim.x + threadIdx.x;
    if (e < EE) atomicAdd(&g_deg[ei[EE + e]], 1);
}

__global__ void k_scan1() {
    __shared__ int s[512];
    int tid = threadIdx.x;
    int n = blockIdx.x * 512 + tid;
    int v = (n < NN) ? g_deg[n] : 0;
    s[tid] = v;
    for (int off = 1; off < 512; off <<= 1) {
        __syncthreads();
        int t = (tid >= off) ? s[tid - off] : 0;
        __syncthreads();
        s[tid] += t;
    }
    if (n < NN) g_rowptr[n] = s[tid] - v;           // local exclusive
    if (tid == 511) g_blocksum[blockIdx.x] = s[511]; // block total
}

__global__ void k_scan2(int nblocks) {
    __shared__ int s[256];
    int tid = threadIdx.x;
    int v = (tid < nblocks) ? g_blocksum[tid] : 0;
    s[tid] = v;
    for (int off = 1; off < 256; off <<= 1) {
        __syncthreads();
        int t = (tid >= off) ? s[tid - off] : 0;
        __syncthreads();
        s[tid] += t;
    }
    g_blockoff[tid] = s[tid] - v;                   // exclusive
}

__global__ void k_scan3() {
    int tid = threadIdx.x;
    int n = blockIdx.x * 512 + tid;
    if (n < NN) {
        int r = g_rowptr[n] + g_blockoff[blockIdx.x];
        g_rowptr[n] = r;
        g_cursor[n] = r;
    }
    if (blockIdx.x == 0 && tid == 0) g_rowptr[NN] = EE;
}

__global__ void k_fill_csr(const int* __restrict__ ei) {
    int e = blockIdx.x * blockDim.x + threadIdx.x;
    if (e < EE) {
        int s = ei[e];
        int d = ei[EE + e];
        int pos = atomicAdd(&g_cursor[d], 1);
        g_csrc[pos] = s;
    }
}

// ---------------- neighbor mean aggregation (warp per node) ---------------
__global__ void k_agg(const float* __restrict__ h, float* __restrict__ agg) {
    int warp = (blockIdx.x * blockDim.x + threadIdx.x) >> 5;
    int lane = threadIdx.x & 31;
    if (warp >= NN) return;
    int beg = g_rowptr[warp];
    int end = g_rowptr[warp + 1];
    const float4* hp = (const float4*)h;
    float4 a0 = make_float4(0.f, 0.f, 0.f, 0.f);
    float4 a1 = make_float4(0.f, 0.f, 0.f, 0.f);
    int i = beg;
    for (; i + 1 < end; i += 2) {
        int s0 = g_csrc[i];
        int s1 = g_csrc[i + 1];
        float4 v0 = hp[s0 * 32 + lane];
        float4 v1 = hp[s1 * 32 + lane];
        a0.x += v0.x; a0.y += v0.y; a0.z += v0.z; a0.w += v0.w;
        a1.x += v1.x; a1.y += v1.y; a1.z += v1.z; a1.w += v1.w;
    }
    if (i < end) {
        int s0 = g_csrc[i];
        float4 v0 = hp[s0 * 32 + lane];
        a0.x += v0.x; a0.y += v0.y; a0.z += v0.z; a0.w += v0.w;
    }
    int d = end - beg;
    float inv = 1.f / (float)(d > 0 ? d : 1);
    float4 r;
    r.x = (a0.x + a1.x) * inv;
    r.y = (a0.y + a1.y) * inv;
    r.z = (a0.z + a1.z) * inv;
    r.w = (a0.w + a1.w) * inv;
    ((float4*)agg)[warp * 32 + lane] = r;
}

// ---------------- GEMM: out[N,128] (+)= A[N,128] @ W[128,128] (+bias) -----
// block: 128 rows x 128 cols, 256 threads (16x16), 8x8 microtile (4x4 quads)
__global__ void k_gemm128(const float* __restrict__ A, const float* __restrict__ W,
                          const float* __restrict__ bias, float* __restrict__ out,
                          int addFlag) {
    __shared__ float Ws[32][128];
    __shared__ float As[128][36];
    int tid = threadIdx.x;
    int tx = tid & 15;
    int ty = tid >> 4;
    int rowBase = blockIdx.x * 128;
    int rbase = ty * 4;
    int cbase = tx * 4;

    float acc[8][8];
#pragma unroll
    for (int i = 0; i < 8; i++)
#pragma unroll
        for (int j = 0; j < 8; j++) acc[i][j] = 0.f;

    for (int kt = 0; kt < 4; kt++) {
        // load W tile (32 k x 128 cols)
#pragma unroll
        for (int i = 0; i < 4; i++) {
            int f = tid + i * 256;          // float4 index, 0..1023
            int k = f >> 5;
            int col = (f & 31) * 4;
            *(float4*)&Ws[k][col] = *(const float4*)&W[(kt * 32 + k) * HH + col];
        }
        // load A tile (128 rows x 32 k)
#pragma unroll
        for (int i = 0; i < 4; i++) {
            int f = tid + i * 256;          // float4 index, 0..1023
            int row = f >> 3;
            int kk = (f & 7) * 4;
            int gr = rowBase + row;
            if (gr > NN - 1) gr = NN - 1;
            *(float4*)&As[row][kk] = *(const float4*)&A[gr * HH + kt * 32 + kk];
        }
        __syncthreads();
#pragma unroll
        for (int k = 0; k < 32; k++) {
            float a[8];
#pragma unroll
            for (int i = 0; i < 4; i++) {
                a[i]     = As[rbase + i][k];
                a[i + 4] = As[rbase + 64 + i][k];
            }
            float4 b0 = *(float4*)&Ws[k][cbase];
            float4 b1 = *(float4*)&Ws[k][cbase + 64];
            float b[8] = {b0.x, b0.y, b0.z, b0.w, b1.x, b1.y, b1.z, b1.w};
#pragma unroll
            for (int i = 0; i < 8; i++)
#pragma unroll
                for (int j = 0; j < 8; j++) acc[i][j] += a[i] * b[j];
        }
        __syncthreads();
    }

    // epilogue
#pragma unroll
    for (int i = 0; i < 8; i++) {
        int gr = rowBase + ((i >> 2) * 64) + rbase + (i & 3);
        if (gr < NN) {
#pragma unroll
            for (int jh = 0; jh < 2; jh++) {
                int c = jh * 64 + cbase;
                float4 v = make_float4(acc[i][jh * 4 + 0], acc[i][jh * 4 + 1],
                                       acc[i][jh * 4 + 2], acc[i][jh * 4 + 3]);
                if (bias) {
                    float4 bb = *(const float4*)&bias[c];
                    v.x += bb.x; v.y += bb.y; v.z += bb.z; v.w += bb.w;
                }
                if (addFlag) {
                    float4 o = *(float4*)&out[gr * HH + c];
                    v.x += o.x; v.y += o.y; v.z += o.z; v.w += o.w;
                }
                *(float4*)&out[gr * HH + c] = v;
            }
        }
    }
}

// ---------------- BatchNorm ------------------------------------------------
__global__ void k_zero_stats() {
    int c = threadIdx.x;
    if (c < HH) { g_sum[c] = 0.f; g_sumsq[c] = 0.f; }
}

__global__ void k_bn_stats(const float* __restrict__ t) {
    int c = threadIdx.x & 127;
    int r = blockIdx.x * 2 + (threadIdx.x >> 7);
    float s = 0.f, q = 0.f;
    int stride = gridDim.x * 2;
#pragma unroll 4
    for (; r < NN; r += stride) {
        float v = t[r * HH + c];
        s += v;
        q += v * v;
    }
    atomicAdd(&g_sum[c], s);
    atomicAdd(&g_sumsq[c], q);
}

__global__ void k_bn_finalize(const float* __restrict__ g, const float* __restrict__ beta) {
    int c = threadIdx.x;
    if (c < HH) {
        float mean = g_sum[c] * (1.f / NN);
        float var = g_sumsq[c] * (1.f / NN) - mean * mean;
        float sc = g[c] * rsqrtf(var + BN_EPS);
        g_scale[c] = sc;
        g_shift[c] = beta[c] - mean * sc;
    }
}

__global__ void k_bn_apply_relu(const float* __restrict__ t, float* __restrict__ h) {
    int idx = blockIdx.x * blockDim.x + threadIdx.x;   // over NN*32 float4s
    if (idx >= NN * 32) return;
    int c4 = idx & 31;
    float4 v = ((const float4*)t)[idx];
    float4 sc = *(const float4*)&g_scale[c4 * 4];
    float4 sh = *(const float4*)&g_shift[c4 * 4];
    float4 r;
    r.x = fmaxf(v.x * sc.x + sh.x, 0.f);
    r.y = fmaxf(v.y * sc.y + sh.y, 0.f);
    r.z = fmaxf(v.z * sc.z + sh.z, 0.f);
    r.w = fmaxf(v.w * sc.w + sh.w, 0.f);
    ((float4*)h)[idx] = r;
}

// ---------------- output GEMM: out[N,40] = A[N,128] @ W[128,40] + b -------
__global__ void k_out_gemm(const float* __restrict__ A, const float* __restrict__ W,
                           const float* __restrict__ bias, float* __restrict__ out) {
    __shared__ float As2[32][128];
    __shared__ float Ws2[HH * CC];
    int tid = threadIdx.x;
    int rowBase = blockIdx.x * 32;
    // load A tile (32x128 = 1024 float4, 4 per thread)
#pragma unroll
    for (int i = 0; i < 4; i++) {
        int f = tid + i * 256;
        int row = f >> 5;
        int kk = (f & 31) * 4;
        int gr = rowBase + row;
        if (gr > NN - 1) gr = NN - 1;
        *(float4*)&As2[row][kk] = *(const float4*)&A[gr * HH + kk];
    }
    // load W (128*40 = 5120 floats = 1280 float4, 5 per thread)
#pragma unroll
    for (int i = 0; i < 5; i++) {
        int f = tid + i * 256;
        *(float4*)&Ws2[f * 4] = *(const float4*)&W[f * 4];
    }
    __syncthreads();

    int row = tid >> 3;
    int cg = tid & 7;          // 8 groups x 5 cols = 40
    float acc[5] = {0.f, 0.f, 0.f, 0.f, 0.f};
#pragma unroll 4
    for (int k = 0; k < HH; k++) {
        float a = As2[row][k];
#pragma unroll
        for (int j = 0; j < 5; j++) acc[j] += a * Ws2[k * CC + cg * 5 + j];
    }
    int gr = rowBase + row;
    if (gr < NN) {
#pragma unroll
        for (int j = 0; j < 5; j++)
            out[gr * CC + cg * 5 + j] = acc[j] + bias[cg * 5 + j];
    }
}

// ---------------- host orchestration ---------------------------------------
extern "C" void kernel_launch(void* const* d_in, const int* in_sizes, int n_in,
                              void* d_out, int out_size) {
    const float* x       = (const float*)d_in[0];
    const float* W_in    = (const float*)d_in[1];
    const float* b_in    = (const float*)d_in[2];
    const float* g_in    = (const float*)d_in[3];
    const float* beta_in = (const float*)d_in[4];
    const float* Wl      = (const float*)d_in[5];
    const float* bl      = (const float*)d_in[6];
    const float* Wr      = (const float*)d_in[7];
    const float* g_bn    = (const float*)d_in[8];
    const float* b_bn    = (const float*)d_in[9];
    const float* W_out   = (const float*)d_in[10];
    const float* b_out   = (const float*)d_in[11];
    const int*   ei      = (const int*)d_in[12];
    float* out = (float*)d_out;

    void *p;
    cudaGetSymbolAddress(&p, g_h);   float* h   = (float*)p;
    cudaGetSymbolAddress(&p, g_tmp); float* tmp = (float*)p;
    cudaGetSymbolAddress(&p, g_agg); float* agg = (float*)p;

    const int SCAN_BLOCKS = (NN + 511) / 512;   // 196

    // build CSR (by dst)
    k_zero_deg<<<(NN + 255) / 256, 256>>>();
    k_hist<<<(EE + 255) / 256, 256>>>(ei);
    k_scan1<<<SCAN_BLOCKS, 512>>>();
    k_scan2<<<1, 256>>>(SCAN_BLOCKS);
    k_scan3<<<SCAN_BLOCKS, 512>>>();
    k_fill_csr<<<(EE + 255) / 256, 256>>>(ei);

    const int GB = (NN + 127) / 128;            // 782 gemm blocks

    // input layer: tmp = x @ W_in + b_in ; BN ; relu -> h
    k_gemm128<<<GB, 256>>>(x, W_in, b_in, tmp, 0);
    k_zero_stats<<<1, 128>>>();
    k_bn_stats<<<256, 256>>>(tmp);
    k_bn_finalize<<<1, 128>>>(g_in, beta_in);
    k_bn_apply_relu<<<(NN * 32 + 255) / 256, 256>>>(tmp, h);

    for (int i = 0; i < LLAYERS; i++) {
        k_agg<<<(NN * 32 + 255) / 256, 256>>>(h, agg);
        k_gemm128<<<GB, 256>>>(agg, Wl + i * HH * HH, bl + i * HH, tmp, 0);
        k_gemm128<<<GB, 256>>>(h, Wr + i * HH * HH, (const float*)0, tmp, 1);
        if (i < LLAYERS - 1) {
            k_zero_stats<<<1, 128>>>();
            k_bn_stats<<<256, 256>>>(tmp);
            k_bn_finalize<<<1, 128>>>(g_bn + i * HH, b_bn + i * HH);
            k_bn_apply_relu<<<(NN * 32 + 255) / 256, 256>>>(tmp, h);
        }
    }

    // output layer from tmp (last layer has no BN)
    k_out_gemm<<<(NN + 31) / 32, 256>>>(tmp, W_out, b_out, out);
}

// round 3
// speedup vs baseline: 1.5639x; 1.5639x over previous
#include <cuda_runtime.h>
#include <cuda_bf16.h>
#include <cstdint>

#define NN 100000
#define EE 1600000
#define HH 128
#define CC 40
#define LLAYERS 4
#define BN_EPS 1e-5f

#define PITCH 136                      // bf16 elements per smem row (128 + 8 pad)
#define PLANE (128 * PITCH)            // elements per 128-row plane

// ---------------- helpers ---------------------------------------------------
__device__ __forceinline__ uint32_t smem_u32(const void* p) {
    uint32_t a;
    asm("{ .reg .u64 t; cvta.to.shared.u64 t, %1; cvt.u32.u64 %0, t; }" : "=r"(a) : "l"(p));
    return a;
}

#define LDSM4(r0, r1, r2, r3, addr)                                             \
    asm volatile("ldmatrix.sync.aligned.m8n8.x4.shared.b16 {%0,%1,%2,%3}, [%4];" \
                 : "=r"(r0), "=r"(r1), "=r"(r2), "=r"(r3) : "r"(addr))

#define MMA16816(c, a0, a1, a2, a3, b0, b1)                                     \
    asm volatile("mma.sync.aligned.m16n8k16.row.col.f32.bf16.bf16.f32 "          \
                 "{%0,%1,%2,%3},{%4,%5,%6,%7},{%8,%9},{%0,%1,%2,%3};"            \
                 : "+f"((c)[0]), "+f"((c)[1]), "+f"((c)[2]), "+f"((c)[3])        \
                 : "r"(a0), "r"(a1), "r"(a2), "r"(a3), "r"(b0), "r"(b1))

// ---------------- scratch (device globals) ----------------------------------
__device__ float g_h[NN * HH];
__device__ float g_tmp[NN * HH];
__device__ float g_agg[NN * HH];
__device__ float g_wt[10 * HH * HH];   // transposed weights: [n][k]
__device__ int   g_deg[NN];
__device__ int   g_rowptr[NN + 1];
__device__ int   g_cursor[NN];
__device__ int   g_csrc[EE];
__device__ int   g_blocksum[256];
__device__ int   g_blockoff[256];
__device__ float g_sum[HH];
__device__ float g_sumsq[HH];
__device__ float g_scale[HH];
__device__ float g_shift[HH];

// ---------------- weight transpose ------------------------------------------
__global__ void k_transpose(const float* __restrict__ W_in, const float* __restrict__ Wl,
                            const float* __restrict__ Wr, const float* __restrict__ W_out) {
    __shared__ float t[32][33];
    int m = blockIdx.z;
    const float* src;
    int stride, ncols;
    if (m == 0)      { src = W_in;                   stride = HH; ncols = HH; }
    else if (m <= 4) { src = Wl + (m - 1) * HH * HH; stride = HH; ncols = HH; }
    else if (m <= 8) { src = Wr + (m - 5) * HH * HH; stride = HH; ncols = HH; }
    else             { src = W_out;                  stride = CC; ncols = CC; }
    float* dst = g_wt + m * HH * HH;
    int bx = blockIdx.x * 32, by = blockIdx.y * 32;
    int tx = threadIdx.x;
    for (int i = threadIdx.y; i < 32; i += 8) {
        int c = bx + tx;
        t[i][tx] = (c < ncols) ? src[(by + i) * stride + c] : 0.f;
    }
    __syncthreads();
    for (int i = threadIdx.y; i < 32; i += 8)
        dst[(bx + i) * HH + by + tx] = t[tx][i];
}

// ---------------- CSR build --------------------------------------------------
__global__ void k_zero_deg() {
    int n = blockIdx.x * blockDim.x + threadIdx.x;
    if (n < NN) g_deg[n] = 0;
}
__global__ void k_hist(const int* __restrict__ ei) {
    int e = blockIdx.x * blockDim.x + threadIdx.x;
    if (e < EE) atomicAdd(&g_deg[ei[EE + e]], 1);
}
__global__ void k_scan1() {
    __shared__ int s[512];
    int tid = threadIdx.x;
    int n = blockIdx.x * 512 + tid;
    int v = (n < NN) ? g_deg[n] : 0;
    s[tid] = v;
    for (int off = 1; off < 512; off <<= 1) {
        __syncthreads();
        int t = (tid >= off) ? s[tid - off] : 0;
        __syncthreads();
        s[tid] += t;
    }
    if (n < NN) g_rowptr[n] = s[tid] - v;
    if (tid == 511) g_blocksum[blockIdx.x] = s[511];
}
__global__ void k_scan2(int nblocks) {
    __shared__ int s[256];
    int tid = threadIdx.x;
    int v = (tid < nblocks) ? g_blocksum[tid] : 0;
    s[tid] = v;
    for (int off = 1; off < 256; off <<= 1) {
        __syncthreads();
        int t = (tid >= off) ? s[tid - off] : 0;
        __syncthreads();
        s[tid] += t;
    }
    g_blockoff[tid] = s[tid] - v;
}
__global__ void k_scan3() {
    int tid = threadIdx.x;
    int n = blockIdx.x * 512 + tid;
    if (n < NN) {
        int r = g_rowptr[n] + g_blockoff[blockIdx.x];
        g_rowptr[n] = r;
        g_cursor[n] = r;
    }
    if (blockIdx.x == 0 && tid == 0) g_rowptr[NN] = EE;
}
__global__ void k_fill_csr(const int* __restrict__ ei) {
    int e = blockIdx.x * blockDim.x + threadIdx.x;
    if (e < EE) {
        int s = ei[e];
        int d = ei[EE + e];
        int pos = atomicAdd(&g_cursor[d], 1);
        g_csrc[pos] = s;
    }
}

// ---------------- neighbor mean aggregation (warp per node) -----------------
__global__ void k_agg(const float* __restrict__ h, float* __restrict__ agg) {
    int warp = (blockIdx.x * blockDim.x + threadIdx.x) >> 5;
    int lane = threadIdx.x & 31;
    if (warp >= NN) return;
    int beg = g_rowptr[warp];
    int end = g_rowptr[warp + 1];
    const float4* hp = (const float4*)h;
    float4 a0 = make_float4(0.f, 0.f, 0.f, 0.f);
    float4 a1 = make_float4(0.f, 0.f, 0.f, 0.f);
    int i = beg;
    for (; i + 1 < end; i += 2) {
        int s0 = g_csrc[i];
        int s1 = g_csrc[i + 1];
        float4 v0 = hp[s0 * 32 + lane];
        float4 v1 = hp[s1 * 32 + lane];
        a0.x += v0.x; a0.y += v0.y; a0.z += v0.z; a0.w += v0.w;
        a1.x += v1.x; a1.y += v1.y; a1.z += v1.z; a1.w += v1.w;
    }
    if (i < end) {
        int s0 = g_csrc[i];
        float4 v0 = hp[s0 * 32 + lane];
        a0.x += v0.x; a0.y += v0.y; a0.z += v0.z; a0.w += v0.w;
    }
    int d = end - beg;
    float inv = 1.f / (float)(d > 0 ? d : 1);
    float4 r;
    r.x = (a0.x + a1.x) * inv;
    r.y = (a0.y + a1.y) * inv;
    r.z = (a0.z + a1.z) * inv;
    r.w = (a0.w + a1.w) * inv;
    ((float4*)agg)[warp * 32 + lane] = r;
}

// ---------------- split-bf16 conversion + smem store ------------------------
__device__ __forceinline__ void cvt_store4(__nv_bfloat16* smbase, int idx, float4 v) {
    __nv_bfloat16 h0 = __float2bfloat16_rn(v.x);
    __nv_bfloat16 h1 = __float2bfloat16_rn(v.y);
    __nv_bfloat16 h2 = __float2bfloat16_rn(v.z);
    __nv_bfloat16 h3 = __float2bfloat16_rn(v.w);
    __nv_bfloat16 l0 = __float2bfloat16_rn(v.x - __bfloat162float(h0));
    __nv_bfloat16 l1 = __float2bfloat16_rn(v.y - __bfloat162float(h1));
    __nv_bfloat16 l2 = __float2bfloat16_rn(v.z - __bfloat162float(h2));
    __nv_bfloat16 l3 = __float2bfloat16_rn(v.w - __bfloat162float(h3));
    uint32_t p01 = (uint32_t)__bfloat16_as_ushort(h0) | ((uint32_t)__bfloat16_as_ushort(h1) << 16);
    uint32_t p23 = (uint32_t)__bfloat16_as_ushort(h2) | ((uint32_t)__bfloat16_as_ushort(h3) << 16);
    uint32_t q01 = (uint32_t)__bfloat16_as_ushort(l0) | ((uint32_t)__bfloat16_as_ushort(l1) << 16);
    uint32_t q23 = (uint32_t)__bfloat16_as_ushort(l2) | ((uint32_t)__bfloat16_as_ushort(l3) << 16);
    *(uint2*)(smbase + idx)         = make_uint2(p01, p23);   // hi plane
    *(uint2*)(smbase + PLANE + idx) = make_uint2(q01, q23);   // lo plane (A) — caller adjusts
}

// ---------------- tensor GEMM: out[N,128] = A0@B0 (+A1@B1) + bias -----------
// smem planes: Ahi[0], Alo[PLANE], Bhi[2*PLANE], Blo[3*PLANE]
__global__ __launch_bounds__(256, 1)
void k_mma(const float* __restrict__ A0, const float* __restrict__ B0t,
           const float* __restrict__ A1, const float* __restrict__ B1t,
           const float* __restrict__ bias, float* __restrict__ out, int statsFlag) {
    extern __shared__ __nv_bfloat16 sm[];
    int tid = threadIdx.x, lane = tid & 31, wid = tid >> 5;
    int wm = wid & 3, wn = wid >> 2;
    int rowBase = blockIdx.x * 128;
    uint32_t smb = smem_u32(sm);

    float acc[2][8][4];
#pragma unroll
    for (int mt = 0; mt < 2; mt++)
#pragma unroll
        for (int nt = 0; nt < 8; nt++)
#pragma unroll
            for (int c = 0; c < 4; c++) acc[mt][nt][c] = 0.f;

    int nsrc = A1 ? 2 : 1;
    for (int s = 0; s < nsrc; s++) {
        if (s > 0) __syncthreads();
        const float* A  = s ? A1 : A0;
        const float* Bt = s ? B1t : B0t;
#pragma unroll
        for (int i = 0; i < 16; i++) {
            int f = tid + i * 256;
            int row = f >> 5, c4 = f & 31;
            int gr = rowBase + row;
            if (gr > NN - 1) gr = NN - 1;
            float4 v = *(const float4*)&A[gr * HH + c4 * 4];
            cvt_store4(sm, row * PITCH + c4 * 4, v);
        }
#pragma unroll
        for (int i = 0; i < 16; i++) {
            int f = tid + i * 256;
            int row = f >> 5, c4 = f & 31;
            float4 v = *(const float4*)&Bt[row * HH + c4 * 4];
            cvt_store4(sm + 2 * PLANE, row * PITCH + c4 * 4, v);
        }
        __syncthreads();

        int arow = wm * 32 + (lane & 15);
        int brow = wn * 64 + (lane & 15);
        int coff = (lane >> 4) * 8;
#pragma unroll 2
        for (int ks = 0; ks < 8; ks++) {
            int col = ks * 16 + coff;
            uint32_t ah[2][4], al[2][4], bh[4][4], bl[4][4];
#pragma unroll
            for (int mt = 0; mt < 2; mt++) {
                uint32_t a = smb + (uint32_t)(((arow + mt * 16) * PITCH + col) * 2);
                LDSM4(ah[mt][0], ah[mt][1], ah[mt][2], ah[mt][3], a);
                LDSM4(al[mt][0], al[mt][1], al[mt][2], al[mt][3], a + PLANE * 2);
            }
#pragma unroll
            for (int n2 = 0; n2 < 4; n2++) {
                uint32_t b = smb + (uint32_t)((2 * PLANE + (brow + n2 * 16) * PITCH + col) * 2);
                LDSM4(bh[n2][0], bh[n2][1], bh[n2][2], bh[n2][3], b);
                LDSM4(bl[n2][0], bl[n2][1], bl[n2][2], bl[n2][3], b + PLANE * 2);
            }
#pragma unroll
            for (int mt = 0; mt < 2; mt++)
#pragma unroll
                for (int nt = 0; nt < 8; nt++) {
                    int n2 = nt >> 1, w = nt & 1;
                    MMA16816(acc[mt][nt], ah[mt][0], ah[mt][1], ah[mt][2], ah[mt][3],
                             bh[n2][w], bh[n2][w + 2]);
                    MMA16816(acc[mt][nt], ah[mt][0], ah[mt][1], ah[mt][2], ah[mt][3],
                             bl[n2][w], bl[n2][w + 2]);
                    MMA16816(acc[mt][nt], al[mt][0], al[mt][1], al[mt][2], al[mt][3],
                             bh[n2][w], bh[n2][w + 2]);
                }
        }
    }

    // epilogue + fused BN stats
    float cs[8][2], cq[8][2];
#pragma unroll
    for (int nt = 0; nt < 8; nt++) { cs[nt][0] = cs[nt][1] = cq[nt][0] = cq[nt][1] = 0.f; }

#pragma unroll
    for (int mt = 0; mt < 2; mt++) {
        int r0 = rowBase + wm * 32 + mt * 16 + (lane >> 2);
#pragma unroll
        for (int nt = 0; nt < 8; nt++) {
            int col = wn * 64 + nt * 8 + (lane & 3) * 2;
            float b0 = bias[col], b1 = bias[col + 1];
            float v0 = acc[mt][nt][0] + b0, v1 = acc[mt][nt][1] + b1;
            float v2 = acc[mt][nt][2] + b0, v3 = acc[mt][nt][3] + b1;
            if (r0 < NN) {
                *(float2*)&out[r0 * HH + col] = make_float2(v0, v1);
                cs[nt][0] += v0; cs[nt][1] += v1;
                cq[nt][0] += v0 * v0; cq[nt][1] += v1 * v1;
            }
            if (r0 + 8 < NN) {
                *(float2*)&out[(r0 + 8) * HH + col] = make_float2(v2, v3);
                cs[nt][0] += v2; cs[nt][1] += v3;
                cq[nt][0] += v2 * v2; cq[nt][1] += v3 * v3;
            }
        }
    }
    if (statsFlag) {
#pragma unroll
        for (int nt = 0; nt < 8; nt++)
#pragma unroll
            for (int j = 0; j < 2; j++) {
                float sv = cs[nt][j], qv = cq[nt][j];
                sv += __shfl_xor_sync(0xFFFFFFFFu, sv, 4);
                sv += __shfl_xor_sync(0xFFFFFFFFu, sv, 8);
                sv += __shfl_xor_sync(0xFFFFFFFFu, sv, 16);
                qv += __shfl_xor_sync(0xFFFFFFFFu, qv, 4);
                qv += __shfl_xor_sync(0xFFFFFFFFu, qv, 8);
                qv += __shfl_xor_sync(0xFFFFFFFFu, qv, 16);
                if (lane < 4) {
                    int col = wn * 64 + nt * 8 + lane * 2 + j;
                    atomicAdd(&g_sum[col], sv);
                    atomicAdd(&g_sumsq[col], qv);
                }
            }
    }
}

// ---------------- tensor output GEMM: out[N,40] = A@Bt + b ------------------
// CTA 128m x 64n. planes: Ahi[0], Alo[PLANE], Bhi[2*PLANE], Blo[2*PLANE+64*PITCH]
__global__ __launch_bounds__(256, 1)
void k_mma_out(const float* __restrict__ A, const float* __restrict__ Bt,
               const float* __restrict__ bias, float* __restrict__ out) {
    extern __shared__ __nv_bfloat16 sm[];
    const int BPL = 64 * PITCH;
    int tid = threadIdx.x, lane = tid & 31, wid = tid >> 5;
    int wm = wid & 3, wn = wid >> 2;
    int rowBase = blockIdx.x * 128;
    uint32_t smb = smem_u32(sm);

    float acc[2][4][4];
#pragma unroll
    for (int mt = 0; mt < 2; mt++)
#pragma unroll
        for (int nt = 0; nt < 4; nt++)
#pragma unroll
            for (int c = 0; c < 4; c++) acc[mt][nt][c] = 0.f;

#pragma unroll
    for (int i = 0; i < 16; i++) {
        int f = tid + i * 256;
        int row = f >> 5, c4 = f & 31;
        int gr = rowBase + row;
        if (gr > NN - 1) gr = NN - 1;
        float4 v = *(const float4*)&A[gr * HH + c4 * 4];
        cvt_store4(sm, row * PITCH + c4 * 4, v);
    }
    // B: 64 rows (cols 0..63 of padded W_out^T)
#pragma unroll
    for (int i = 0; i < 8; i++) {
        int f = tid + i * 256;
        int row = f >> 5, c4 = f & 31;
        float4 v = *(const float4*)&Bt[row * HH + c4 * 4];
        __nv_bfloat16 h0 = __float2bfloat16_rn(v.x), h1 = __float2bfloat16_rn(v.y);
        __nv_bfloat16 h2 = __float2bfloat16_rn(v.z), h3 = __float2bfloat16_rn(v.w);
        __nv_bfloat16 l0 = __float2bfloat16_rn(v.x - __bfloat162float(h0));
        __nv_bfloat16 l1 = __float2bfloat16_rn(v.y - __bfloat162float(h1));
        __nv_bfloat16 l2 = __float2bfloat16_rn(v.z - __bfloat162float(h2));
        __nv_bfloat16 l3 = __float2bfloat16_rn(v.w - __bfloat162float(h3));
        uint32_t p01 = (uint32_t)__bfloat16_as_ushort(h0) | ((uint32_t)__bfloat16_as_ushort(h1) << 16);
        uint32_t p23 = (uint32_t)__bfloat16_as_ushort(h2) | ((uint32_t)__bfloat16_as_ushort(h3) << 16);
        uint32_t q01 = (uint32_t)__bfloat16_as_ushort(l0) | ((uint32_t)__bfloat16_as_ushort(l1) << 16);
        uint32_t q23 = (uint32_t)__bfloat16_as_ushort(l2) | ((uint32_t)__bfloat16_as_ushort(l3) << 16);
        int idx = 2 * PLANE + row * PITCH + c4 * 4;
        *(uint2*)(sm + idx)       = make_uint2(p01, p23);
        *(uint2*)(sm + idx + BPL) = make_uint2(q01, q23);
    }
    __syncthreads();

    int arow = wm * 32 + (lane & 15);
    int brow = wn * 32 + (lane & 15);
    int coff = (lane >> 4) * 8;
#pragma unroll 2
    for (int ks = 0; ks < 8; ks++) {
        int col = ks * 16 + coff;
        uint32_t ah[2][4], al[2][4], bh[2][4], bl[2][4];
#pragma unroll
        for (int mt = 0; mt < 2; mt++) {
            uint32_t a = smb + (uint32_t)(((arow + mt * 16) * PITCH + col) * 2);
            LDSM4(ah[mt][0], ah[mt][1], ah[mt][2], ah[mt][3], a);
            LDSM4(al[mt][0], al[mt][1], al[mt][2], al[mt][3], a + PLANE * 2);
        }
#pragma unroll
        for (int n2 = 0; n2 < 2; n2++) {
            uint32_t b = smb + (uint32_t)((2 * PLANE + (brow + n2 * 16) * PITCH + col) * 2);
            LDSM4(bh[n2][0], bh[n2][1], bh[n2][2], bh[n2][3], b);
            LDSM4(bl[n2][0], bl[n2][1], bl[n2][2], bl[n2][3], b + BPL * 2);
        }
#pragma unroll
        for (int mt = 0; mt < 2; mt++)
#pragma unroll
            for (int nt = 0; nt < 4; nt++) {
                int n2 = nt >> 1, w = nt & 1;
                MMA16816(acc[mt][nt], ah[mt][0], ah[mt][1], ah[mt][2], ah[mt][3],
                         bh[n2][w], bh[n2][w + 2]);
                MMA16816(acc[mt][nt], ah[mt][0], ah[mt][1], ah[mt][2], ah[mt][3],
                         bl[n2][w], bl[n2][w + 2]);
                MMA16816(acc[mt][nt], al[mt][0], al[mt][1], al[mt][2], al[mt][3],
                         bh[n2][w], bh[n2][w + 2]);
            }
    }

#pragma unroll
    for (int mt = 0; mt < 2; mt++) {
        int r0 = rowBase + wm * 32 + mt * 16 + (lane >> 2);
#pragma unroll
        for (int nt = 0; nt < 4; nt++) {
            int col = wn * 32 + nt * 8 + (lane & 3) * 2;
            if (col < CC) {
                float b0 = bias[col], b1 = bias[col + 1];
                if (r0 < NN)
                    *(float2*)&out[r0 * CC + col] =
                        make_float2(acc[mt][nt][0] + b0, acc[mt][nt][1] + b1);
                if (r0 + 8 < NN)
                    *(float2*)&out[(r0 + 8) * CC + col] =
                        make_float2(acc[mt][nt][2] + b0, acc[mt][nt][3] + b1);
            }
        }
    }
}

// ---------------- BatchNorm -------------------------------------------------
__global__ void k_zero_stats() {
    int c = threadIdx.x;
    if (c < HH) { g_sum[c] = 0.f; g_sumsq[c] = 0.f; }
}
__global__ void k_bn_finalize(const float* __restrict__ g, const float* __restrict__ beta) {
    int c = threadIdx.x;
    if (c < HH) {
        float mean = g_sum[c] * (1.f / NN);
        float var = g_sumsq[c] * (1.f / NN) - mean * mean;
        float sc = g[c] * rsqrtf(var + BN_EPS);
        g_scale[c] = sc;
        g_shift[c] = beta[c] - mean * sc;
    }
}
__global__ void k_bn_apply_relu(const float* __restrict__ t, float* __restrict__ h) {
    int idx = blockIdx.x * blockDim.x + threadIdx.x;
    if (idx >= NN * 32) return;
    int c4 = idx & 31;
    float4 v = ((const float4*)t)[idx];
    float4 sc = *(const float4*)&g_scale[c4 * 4];
    float4 sh = *(const float4*)&g_shift[c4 * 4];
    float4 r;
    r.x = fmaxf(v.x * sc.x + sh.x, 0.f);
    r.y = fmaxf(v.y * sc.y + sh.y, 0.f);
    r.z = fmaxf(v.z * sc.z + sh.z, 0.f);
    r.w = fmaxf(v.w * sc.w + sh.w, 0.f);
    ((float4*)h)[idx] = r;
}

// ---------------- host orchestration ----------------------------------------
extern "C" void kernel_launch(void* const* d_in, const int* in_sizes, int n_in,
                              void* d_out, int out_size) {
    const float* x       = (const float*)d_in[0];
    const float* W_in    = (const float*)d_in[1];
    const float* b_in    = (const float*)d_in[2];
    const float* g_in    = (const float*)d_in[3];
    const float* beta_in = (const float*)d_in[4];
    const float* Wl      = (const float*)d_in[5];
    const float* bl      = (const float*)d_in[6];
    const float* Wr      = (const float*)d_in[7];
    const float* g_bn    = (const float*)d_in[8];
    const float* b_bn    = (const float*)d_in[9];
    const float* W_out   = (const float*)d_in[10];
    const float* b_out   = (const float*)d_in[11];
    const int*   ei      = (const int*)d_in[12];
    float* out = (float*)d_out;

    void* p;
    cudaGetSymbolAddress(&p, g_h);   float* h   = (float*)p;
    cudaGetSymbolAddress(&p, g_tmp); float* tmp = (float*)p;
    cudaGetSymbolAddress(&p, g_agg); float* agg = (float*)p;
    cudaGetSymbolAddress(&p, g_wt);  float* wt  = (float*)p;

    const int GEMM_SMEM = 4 * PLANE * 2;                       // 139264 B
    const int OUT_SMEM  = (2 * PLANE + 2 * 64 * PITCH) * 2;    // 104448 B
    cudaFuncSetAttribute(k_mma, cudaFuncAttributeMaxDynamicSharedMemorySize, GEMM_SMEM);
    cudaFuncSetAttribute(k_mma_out, cudaFuncAttributeMaxDynamicSharedMemorySize, OUT_SMEM);

    const int SCAN_BLOCKS = (NN + 511) / 512;

    k_transpose<<<dim3(4, 4, 10), dim3(32, 8)>>>(W_in, Wl, Wr, W_out);

    k_zero_deg<<<(NN + 255) / 256, 256>>>();
    k_hist<<<(EE + 255) / 256, 256>>>(ei);
    k_scan1<<<SCAN_BLOCKS, 512>>>();
    k_scan2<<<1, 256>>>(SCAN_BLOCKS);
    k_scan3<<<SCAN_BLOCKS, 512>>>();
    k_fill_csr<<<(EE + 255) / 256, 256>>>(ei);

    const int GB = (NN + 127) / 128;   // 782

    // input layer
    k_zero_stats<<<1, 128>>>();
    k_mma<<<GB, 256, GEMM_SMEM>>>(x, wt, (const float*)0, (const float*)0, b_in, tmp, 1);
    k_bn_finalize<<<1, 128>>>(g_in, beta_in);
    k_bn_apply_relu<<<(NN * 32 + 255) / 256, 256>>>(tmp, h);

    for (int i = 0; i < LLAYERS; i++) {
        k_agg<<<(NN * 32 + 255) / 256, 256>>>(h, agg);
        int stats = (i < LLAYERS - 1) ? 1 : 0;
        if (stats) k_zero_stats<<<1, 128>>>();
        k_mma<<<GB, 256, GEMM_SMEM>>>(agg, wt + (1 + i) * HH * HH,
                                      h,   wt + (5 + i) * HH * HH,
                                      bl + i * HH, tmp, stats);
        if (stats) {
            k_bn_finalize<<<1, 128>>>(g_bn + i * HH, b_bn + i * HH);
            k_bn_apply_relu<<<(NN * 32 + 255) / 256, 256>>>(tmp, h);
        }
    }

    k_mma_out<<<GB, 256, OUT_SMEM>>>(tmp, wt + 9 * HH * HH, b_out, out);
}

// round 4
// speedup vs baseline: 1.7027x; 1.0887x over previous
#include <cuda_runtime.h>
#include <cuda_bf16.h>
#include <cuda_fp16.h>
#include <cstdint>

#define NN 100000
#define EE 1600000
#define HH 128
#define CC 40
#define LLAYERS 4
#define BN_EPS 1e-5f

#define PITCH 136                      // bf16 elements per smem row (128 + 8 pad)
#define PLANE (128 * PITCH)            // elements per 128-row plane

// ---------------- helpers ---------------------------------------------------
__device__ __forceinline__ uint32_t smem_u32(const void* p) {
    uint32_t a;
    asm("{ .reg .u64 t; cvta.to.shared.u64 t, %1; cvt.u32.u64 %0, t; }" : "=r"(a) : "l"(p));
    return a;
}

#define LDSM4(r0, r1, r2, r3, addr)                                             \
    asm volatile("ldmatrix.sync.aligned.m8n8.x4.shared.b16 {%0,%1,%2,%3}, [%4];" \
                 : "=r"(r0), "=r"(r1), "=r"(r2), "=r"(r3) : "r"(addr))

#define MMA16816(c, a0, a1, a2, a3, b0, b1)                                     \
    asm volatile("mma.sync.aligned.m16n8k16.row.col.f32.bf16.bf16.f32 "          \
                 "{%0,%1,%2,%3},{%4,%5,%6,%7},{%8,%9},{%0,%1,%2,%3};"            \
                 : "+f"((c)[0]), "+f"((c)[1]), "+f"((c)[2]), "+f"((c)[3])        \
                 : "r"(a0), "r"(a1), "r"(a2), "r"(a3), "r"(b0), "r"(b1))

// ---------------- scratch (device globals) ----------------------------------
__device__ __half g_h16[NN * HH];      // post-BN/ReLU activations (fp16)
__device__ float g_tmp[NN * HH];
__device__ float g_agg[NN * HH];
__device__ float g_wt[10 * HH * HH];   // transposed weights: [n][k]
__device__ int   g_deg[NN];
__device__ int   g_rowptr[NN + 1];
__device__ int   g_cursor[NN];
__device__ int   g_csrc[EE];
__device__ int   g_blocksum[256];
__device__ int   g_blockoff[256];
__device__ float g_sum[HH];
__device__ float g_sumsq[HH];
__device__ float g_scale[HH];
__device__ float g_shift[HH];

// ---------------- weight transpose ------------------------------------------
__global__ void k_transpose(const float* __restrict__ W_in, const float* __restrict__ Wl,
                            const float* __restrict__ Wr, const float* __restrict__ W_out) {
    __shared__ float t[32][33];
    int m = blockIdx.z;
    const float* src;
    int stride, ncols;
    if (m == 0)      { src = W_in;                   stride = HH; ncols = HH; }
    else if (m <= 4) { src = Wl + (m - 1) * HH * HH; stride = HH; ncols = HH; }
    else if (m <= 8) { src = Wr + (m - 5) * HH * HH; stride = HH; ncols = HH; }
    else             { src = W_out;                  stride = CC; ncols = CC; }
    float* dst = g_wt + m * HH * HH;
    int bx = blockIdx.x * 32, by = blockIdx.y * 32;
    int tx = threadIdx.x;
    for (int i = threadIdx.y; i < 32; i += 8) {
        int c = bx + tx;
        t[i][tx] = (c < ncols) ? src[(by + i) * stride + c] : 0.f;
    }
    __syncthreads();
    for (int i = threadIdx.y; i < 32; i += 8)
        dst[(bx + i) * HH + by + tx] = t[tx][i];
}

// ---------------- CSR build --------------------------------------------------
__global__ void k_zero_deg() {
    int n = blockIdx.x * blockDim.x + threadIdx.x;
    if (n < NN) g_deg[n] = 0;
}
__global__ void k_hist(const int* __restrict__ ei) {
    int e = blockIdx.x * blockDim.x + threadIdx.x;
    if (e < EE) atomicAdd(&g_deg[ei[EE + e]], 1);
}
__global__ void k_scan1() {
    __shared__ int s[512];
    int tid = threadIdx.x;
    int n = blockIdx.x * 512 + tid;
    int v = (n < NN) ? g_deg[n] : 0;
    s[tid] = v;
    for (int off = 1; off < 512; off <<= 1) {
        __syncthreads();
        int t = (tid >= off) ? s[tid - off] : 0;
        __syncthreads();
        s[tid] += t;
    }
    if (n < NN) g_rowptr[n] = s[tid] - v;
    if (tid == 511) g_blocksum[blockIdx.x] = s[511];
}
__global__ void k_scan2(int nblocks) {
    __shared__ int s[256];
    int tid = threadIdx.x;
    int v = (tid < nblocks) ? g_blocksum[tid] : 0;
    s[tid] = v;
    for (int off = 1; off < 256; off <<= 1) {
        __syncthreads();
        int t = (tid >= off) ? s[tid - off] : 0;
        __syncthreads();
        s[tid] += t;
    }
    g_blockoff[tid] = s[tid] - v;
}
__global__ void k_scan3() {
    int tid = threadIdx.x;
    int n = blockIdx.x * 512 + tid;
    if (n < NN) {
        int r = g_rowptr[n] + g_blockoff[blockIdx.x];
        g_rowptr[n] = r;
        g_cursor[n] = r;
    }
    if (blockIdx.x == 0 && tid == 0) g_rowptr[NN] = EE;
}
__global__ void k_fill_csr(const int* __restrict__ ei) {
    int e = blockIdx.x * blockDim.x + threadIdx.x;
    if (e < EE) {
        int s = ei[e];
        int d = ei[EE + e];
        int pos = atomicAdd(&g_cursor[d], 1);
        g_csrc[pos] = s;
    }
}

// ---------------- neighbor mean aggregation (warp per node, fp16 gather) ----
__global__ void k_agg(const __half* __restrict__ h, float* __restrict__ agg) {
    int warp = (blockIdx.x * blockDim.x + threadIdx.x) >> 5;
    int lane = threadIdx.x & 31;
    if (warp >= NN) return;
    int beg = g_rowptr[warp];
    int end = g_rowptr[warp + 1];
    const uint2* hp = (const uint2*)h;         // 4 halves per uint2, 32 per row
    float4 a0 = make_float4(0.f, 0.f, 0.f, 0.f);
    float4 a1 = make_float4(0.f, 0.f, 0.f, 0.f);
    int i = beg;
    for (; i + 1 < end; i += 2) {
        int s0 = g_csrc[i];
        int s1 = g_csrc[i + 1];
        uint2 u0 = hp[s0 * 32 + lane];
        uint2 u1 = hp[s1 * 32 + lane];
        float2 f00 = __half22float2(*(__half2*)&u0.x);
        float2 f01 = __half22float2(*(__half2*)&u0.y);
        float2 f10 = __half22float2(*(__half2*)&u1.x);
        float2 f11 = __half22float2(*(__half2*)&u1.y);
        a0.x += f00.x; a0.y += f00.y; a0.z += f01.x; a0.w += f01.y;
        a1.x += f10.x; a1.y += f10.y; a1.z += f11.x; a1.w += f11.y;
    }
    if (i < end) {
        int s0 = g_csrc[i];
        uint2 u0 = hp[s0 * 32 + lane];
        float2 f00 = __half22float2(*(__half2*)&u0.x);
        float2 f01 = __half22float2(*(__half2*)&u0.y);
        a0.x += f00.x; a0.y += f00.y; a0.z += f01.x; a0.w += f01.y;
    }
    int d = end - beg;
    float inv = 1.f / (float)(d > 0 ? d : 1);
    float4 r;
    r.x = (a0.x + a1.x) * inv;
    r.y = (a0.y + a1.y) * inv;
    r.z = (a0.z + a1.z) * inv;
    r.w = (a0.w + a1.w) * inv;
    ((float4*)agg)[warp * 32 + lane] = r;
}

// ---------------- split-bf16 conversion + smem store ------------------------
__device__ __forceinline__ void cvt_store4(__nv_bfloat16* smbase, int idx, float4 v) {
    __nv_bfloat16 h0 = __float2bfloat16_rn(v.x);
    __nv_bfloat16 h1 = __float2bfloat16_rn(v.y);
    __nv_bfloat16 h2 = __float2bfloat16_rn(v.z);
    __nv_bfloat16 h3 = __float2bfloat16_rn(v.w);
    __nv_bfloat16 l0 = __float2bfloat16_rn(v.x - __bfloat162float(h0));
    __nv_bfloat16 l1 = __float2bfloat16_rn(v.y - __bfloat162float(h1));
    __nv_bfloat16 l2 = __float2bfloat16_rn(v.z - __bfloat162float(h2));
    __nv_bfloat16 l3 = __float2bfloat16_rn(v.w - __bfloat162float(h3));
    uint32_t p01 = (uint32_t)__bfloat16_as_ushort(h0) | ((uint32_t)__bfloat16_as_ushort(h1) << 16);
    uint32_t p23 = (uint32_t)__bfloat16_as_ushort(h2) | ((uint32_t)__bfloat16_as_ushort(h3) << 16);
    uint32_t q01 = (uint32_t)__bfloat16_as_ushort(l0) | ((uint32_t)__bfloat16_as_ushort(l1) << 16);
    uint32_t q23 = (uint32_t)__bfloat16_as_ushort(l2) | ((uint32_t)__bfloat16_as_ushort(l3) << 16);
    *(uint2*)(smbase + idx)         = make_uint2(p01, p23);
    *(uint2*)(smbase + PLANE + idx) = make_uint2(q01, q23);
}

// ---------------- tensor GEMM: out[N,128] = A0@B0 (+A1@B1) + bias -----------
// A0: fp32, A1: fp16 (optional). smem: Ahi[0], Alo[PLANE], Bhi[2P], Blo[3P]
__global__ __launch_bounds__(256, 1)
void k_mma(const float* __restrict__ A0, const float* __restrict__ B0t,
           const __half* __restrict__ A1h, const float* __restrict__ B1t,
           const float* __restrict__ bias, float* __restrict__ out, int statsFlag) {
    extern __shared__ __nv_bfloat16 sm[];
    int tid = threadIdx.x, lane = tid & 31, wid = tid >> 5;
    int wm = wid & 3, wn = wid >> 2;
    int rowBase = blockIdx.x * 128;
    uint32_t smb = smem_u32(sm);

    float acc[2][8][4];
#pragma unroll
    for (int mt = 0; mt < 2; mt++)
#pragma unroll
        for (int nt = 0; nt < 8; nt++)
#pragma unroll
            for (int c = 0; c < 4; c++) acc[mt][nt][c] = 0.f;

    int nsrc = A1h ? 2 : 1;
    for (int s = 0; s < nsrc; s++) {
        if (s > 0) __syncthreads();
        const float* Bt = s ? B1t : B0t;
#pragma unroll
        for (int i = 0; i < 16; i++) {
            int f = tid + i * 256;
            int row = f >> 5, c4 = f & 31;
            int gr = rowBase + row;
            if (gr > NN - 1) gr = NN - 1;
            float4 v;
            if (s == 0) {
                v = *(const float4*)&A0[gr * HH + c4 * 4];
            } else {
                uint2 u = *(const uint2*)&A1h[gr * HH + c4 * 4];
                float2 f01 = __half22float2(*(__half2*)&u.x);
                float2 f23 = __half22float2(*(__half2*)&u.y);
                v = make_float4(f01.x, f01.y, f23.x, f23.y);
            }
            cvt_store4(sm, row * PITCH + c4 * 4, v);
        }
#pragma unroll
        for (int i = 0; i < 16; i++) {
            int f = tid + i * 256;
            int row = f >> 5, c4 = f & 31;
            float4 v = *(const float4*)&Bt[row * HH + c4 * 4];
            cvt_store4(sm + 2 * PLANE, row * PITCH + c4 * 4, v);
        }
        __syncthreads();

        int arow = wm * 32 + (lane & 15);
        int brow = wn * 64 + (lane & 15);
        int coff = (lane >> 4) * 8;
#pragma unroll 2
        for (int ks = 0; ks < 8; ks++) {
            int col = ks * 16 + coff;
            uint32_t ah[2][4], al[2][4], bh[4][4], bl[4][4];
#pragma unroll
            for (int mt = 0; mt < 2; mt++) {
                uint32_t a = smb + (uint32_t)(((arow + mt * 16) * PITCH + col) * 2);
                LDSM4(ah[mt][0], ah[mt][1], ah[mt][2], ah[mt][3], a);
                LDSM4(al[mt][0], al[mt][1], al[mt][2], al[mt][3], a + PLANE * 2);
            }
#pragma unroll
            for (int n2 = 0; n2 < 4; n2++) {
                uint32_t b = smb + (uint32_t)((2 * PLANE + (brow + n2 * 16) * PITCH + col) * 2);
                LDSM4(bh[n2][0], bh[n2][1], bh[n2][2], bh[n2][3], b);
                LDSM4(bl[n2][0], bl[n2][1], bl[n2][2], bl[n2][3], b + PLANE * 2);
            }
#pragma unroll
            for (int mt = 0; mt < 2; mt++)
#pragma unroll
                for (int nt = 0; nt < 8; nt++) {
                    int n2 = nt >> 1, w = nt & 1;
                    MMA16816(acc[mt][nt], ah[mt][0], ah[mt][1], ah[mt][2], ah[mt][3],
                             bh[n2][w], bh[n2][w + 2]);
                    MMA16816(acc[mt][nt], ah[mt][0], ah[mt][1], ah[mt][2], ah[mt][3],
                             bl[n2][w], bl[n2][w + 2]);
                    MMA16816(acc[mt][nt], al[mt][0], al[mt][1], al[mt][2], al[mt][3],
                             bh[n2][w], bh[n2][w + 2]);
                }
        }
    }

    // epilogue + fused BN stats
    float cs[8][2], cq[8][2];
#pragma unroll
    for (int nt = 0; nt < 8; nt++) { cs[nt][0] = cs[nt][1] = cq[nt][0] = cq[nt][1] = 0.f; }

#pragma unroll
    for (int mt = 0; mt < 2; mt++) {
        int r0 = rowBase + wm * 32 + mt * 16 + (lane >> 2);
#pragma unroll
        for (int nt = 0; nt < 8; nt++) {
            int col = wn * 64 + nt * 8 + (lane & 3) * 2;
            float b0 = bias[col], b1 = bias[col + 1];
            float v0 = acc[mt][nt][0] + b0, v1 = acc[mt][nt][1] + b1;
            float v2 = acc[mt][nt][2] + b0, v3 = acc[mt][nt][3] + b1;
            if (r0 < NN) {
                *(float2*)&out[r0 * HH + col] = make_float2(v0, v1);
                cs[nt][0] += v0; cs[nt][1] += v1;
                cq[nt][0] += v0 * v0; cq[nt][1] += v1 * v1;
            }
            if (r0 + 8 < NN) {
                *(float2*)&out[(r0 + 8) * HH + col] = make_float2(v2, v3);
                cs[nt][0] += v2; cs[nt][1] += v3;
                cq[nt][0] += v2 * v2; cq[nt][1] += v3 * v3;
            }
        }
    }
    if (statsFlag) {
#pragma unroll
        for (int nt = 0; nt < 8; nt++)
#pragma unroll
            for (int j = 0; j < 2; j++) {
                float sv = cs[nt][j], qv = cq[nt][j];
                sv += __shfl_xor_sync(0xFFFFFFFFu, sv, 4);
                sv += __shfl_xor_sync(0xFFFFFFFFu, sv, 8);
                sv += __shfl_xor_sync(0xFFFFFFFFu, sv, 16);
                qv += __shfl_xor_sync(0xFFFFFFFFu, qv, 4);
                qv += __shfl_xor_sync(0xFFFFFFFFu, qv, 8);
                qv += __shfl_xor_sync(0xFFFFFFFFu, qv, 16);
                if (lane < 4) {
                    int col = wn * 64 + nt * 8 + lane * 2 + j;
                    atomicAdd(&g_sum[col], sv);
                    atomicAdd(&g_sumsq[col], qv);
                }
            }
    }
}

// ---------------- tensor output GEMM: out[N,40] = A@Bt + b ------------------
__global__ __launch_bounds__(256, 1)
void k_mma_out(const float* __restrict__ A, const float* __restrict__ Bt,
               const float* __restrict__ bias, float* __restrict__ out) {
    extern __shared__ __nv_bfloat16 sm[];
    const int BPL = 64 * PITCH;
    int tid = threadIdx.x, lane = tid & 31, wid = tid >> 5;
    int wm = wid & 3, wn = wid >> 2;
    int rowBase = blockIdx.x * 128;
    uint32_t smb = smem_u32(sm);

    float acc[2][4][4];
#pragma unroll
    for (int mt = 0; mt < 2; mt++)
#pragma unroll
        for (int nt = 0; nt < 4; nt++)
#pragma unroll
            for (int c = 0; c < 4; c++) acc[mt][nt][c] = 0.f;

#pragma unroll
    for (int i = 0; i < 16; i++) {
        int f = tid + i * 256;
        int row = f >> 5, c4 = f & 31;
        int gr = rowBase + row;
        if (gr > NN - 1) gr = NN - 1;
        float4 v = *(const float4*)&A[gr * HH + c4 * 4];
        cvt_store4(sm, row * PITCH + c4 * 4, v);
    }
#pragma unroll
    for (int i = 0; i < 8; i++) {
        int f = tid + i * 256;
        int row = f >> 5, c4 = f & 31;
        float4 v = *(const float4*)&Bt[row * HH + c4 * 4];
        __nv_bfloat16 h0 = __float2bfloat16_rn(v.x), h1 = __float2bfloat16_rn(v.y);
        __nv_bfloat16 h2 = __float2bfloat16_rn(v.z), h3 = __float2bfloat16_rn(v.w);
        __nv_bfloat16 l0 = __float2bfloat16_rn(v.x - __bfloat162float(h0));
        __nv_bfloat16 l1 = __float2bfloat16_rn(v.y - __bfloat162float(h1));
        __nv_bfloat16 l2 = __float2bfloat16_rn(v.z - __bfloat162float(h2));
        __nv_bfloat16 l3 = __float2bfloat16_rn(v.w - __bfloat162float(h3));
        uint32_t p01 = (uint32_t)__bfloat16_as_ushort(h0) | ((uint32_t)__bfloat16_as_ushort(h1) << 16);
        uint32_t p23 = (uint32_t)__bfloat16_as_ushort(h2) | ((uint32_t)__bfloat16_as_ushort(h3) << 16);
        uint32_t q01 = (uint32_t)__bfloat16_as_ushort(l0) | ((uint32_t)__bfloat16_as_ushort(l1) << 16);
        uint32_t q23 = (uint32_t)__bfloat16_as_ushort(l2) | ((uint32_t)__bfloat16_as_ushort(l3) << 16);
        int idx = 2 * PLANE + row * PITCH + c4 * 4;
        *(uint2*)(sm + idx)       = make_uint2(p01, p23);
        *(uint2*)(sm + idx + BPL) = make_uint2(q01, q23);
    }
    __syncthreads();

    int arow = wm * 32 + (lane & 15);
    int brow = wn * 32 + (lane & 15);
    int coff = (lane >> 4) * 8;
#pragma unroll 2
    for (int ks = 0; ks < 8; ks++) {
        int col = ks * 16 + coff;
        uint32_t ah[2][4], al[2][4], bh[2][4], bl[2][4];
#pragma unroll
        for (int mt = 0; mt < 2; mt++) {
            uint32_t a = smb + (uint32_t)(((arow + mt * 16) * PITCH + col) * 2);
            LDSM4(ah[mt][0], ah[mt][1], ah[mt][2], ah[mt][3], a);
            LDSM4(al[mt][0], al[mt][1], al[mt][2], al[mt][3], a + PLANE * 2);
        }
#pragma unroll
        for (int n2 = 0; n2 < 2; n2++) {
            uint32_t b = smb + (uint32_t)((2 * PLANE + (brow + n2 * 16) * PITCH + col) * 2);
            LDSM4(bh[n2][0], bh[n2][1], bh[n2][2], bh[n2][3], b);
            LDSM4(bl[n2][0], bl[n2][1], bl[n2][2], bl[n2][3], b + BPL * 2);
        }
#pragma unroll
        for (int mt = 0; mt < 2; mt++)
#pragma unroll
            for (int nt = 0; nt < 4; nt++) {
                int n2 = nt >> 1, w = nt & 1;
                MMA16816(acc[mt][nt], ah[mt][0], ah[mt][1], ah[mt][2], ah[mt][3],
                         bh[n2][w], bh[n2][w + 2]);
                MMA16816(acc[mt][nt], ah[mt][0], ah[mt][1], ah[mt][2], ah[mt][3],
                         bl[n2][w], bl[n2][w + 2]);
                MMA16816(acc[mt][nt], al[mt][0], al[mt][1], al[mt][2], al[mt][3],
                         bh[n2][w], bh[n2][w + 2]);
            }
    }

#pragma unroll
    for (int mt = 0; mt < 2; mt++) {
        int r0 = rowBase + wm * 32 + mt * 16 + (lane >> 2);
#pragma unroll
        for (int nt = 0; nt < 4; nt++) {
            int col = wn * 32 + nt * 8 + (lane & 3) * 2;
            if (col < CC) {
                float b0 = bias[col], b1 = bias[col + 1];
                if (r0 < NN)
                    *(float2*)&out[r0 * CC + col] =
                        make_float2(acc[mt][nt][0] + b0, acc[mt][nt][1] + b1);
                if (r0 + 8 < NN)
                    *(float2*)&out[(r0 + 8) * CC + col] =
                        make_float2(acc[mt][nt][2] + b0, acc[mt][nt][3] + b1);
            }
        }
    }
}

// ---------------- BatchNorm -------------------------------------------------
__global__ void k_zero_stats() {
    int c = threadIdx.x;
    if (c < HH) { g_sum[c] = 0.f; g_sumsq[c] = 0.f; }
}
__global__ void k_bn_finalize(const float* __restrict__ g, const float* __restrict__ beta) {
    int c = threadIdx.x;
    if (c < HH) {
        float mean = g_sum[c] * (1.f / NN);
        float var = g_sumsq[c] * (1.f / NN) - mean * mean;
        float sc = g[c] * rsqrtf(var + BN_EPS);
        g_scale[c] = sc;
        g_shift[c] = beta[c] - mean * sc;
    }
}
__global__ void k_bn_apply_relu(const float* __restrict__ t, __half* __restrict__ h) {
    int idx = blockIdx.x * blockDim.x + threadIdx.x;   // over NN*32 groups of 4
    if (idx >= NN * 32) return;
    int c4 = idx & 31;
    float4 v = ((const float4*)t)[idx];
    float4 sc = *(const float4*)&g_scale[c4 * 4];
    float4 sh = *(const float4*)&g_shift[c4 * 4];
    float r0 = fmaxf(v.x * sc.x + sh.x, 0.f);
    float r1 = fmaxf(v.y * sc.y + sh.y, 0.f);
    float r2 = fmaxf(v.z * sc.z + sh.z, 0.f);
    float r3 = fmaxf(v.w * sc.w + sh.w, 0.f);
    __half2 p0 = __floats2half2_rn(r0, r1);
    __half2 p1 = __floats2half2_rn(r2, r3);
    uint2 st = make_uint2(*(uint32_t*)&p0, *(uint32_t*)&p1);
    ((uint2*)h)[idx] = st;
}

// ---------------- host orchestration ----------------------------------------
extern "C" void kernel_launch(void* const* d_in, const int* in_sizes, int n_in,
                              void* d_out, int out_size) {
    const float* x       = (const float*)d_in[0];
    const float* W_in    = (const float*)d_in[1];
    const float* b_in    = (const float*)d_in[2];
    const float* g_in    = (const float*)d_in[3];
    const float* beta_in = (const float*)d_in[4];
    const float* Wl      = (const float*)d_in[5];
    const float* bl      = (const float*)d_in[6];
    const float* Wr      = (const float*)d_in[7];
    const float* g_bn    = (const float*)d_in[8];
    const float* b_bn    = (const float*)d_in[9];
    const float* W_out   = (const float*)d_in[10];
    const float* b_out   = (const float*)d_in[11];
    const int*   ei      = (const int*)d_in[12];
    float* out = (float*)d_out;

    void* p;
    cudaGetSymbolAddress(&p, g_h16); __half* h16 = (__half*)p;
    cudaGetSymbolAddress(&p, g_tmp); float* tmp = (float*)p;
    cudaGetSymbolAddress(&p, g_agg); float* agg = (float*)p;
    cudaGetSymbolAddress(&p, g_wt);  float* wt  = (float*)p;

    const int GEMM_SMEM = 4 * PLANE * 2;                       // 139264 B
    const int OUT_SMEM  = (2 * PLANE + 2 * 64 * PITCH) * 2;    // 104448 B
    cudaFuncSetAttribute(k_mma, cudaFuncAttributeMaxDynamicSharedMemorySize, GEMM_SMEM);
    cudaFuncSetAttribute(k_mma_out, cudaFuncAttributeMaxDynamicSharedMemorySize, OUT_SMEM);

    const int SCAN_BLOCKS = (NN + 511) / 512;

    k_transpose<<<dim3(4, 4, 10), dim3(32, 8)>>>(W_in, Wl, Wr, W_out);

    k_zero_deg<<<(NN + 255) / 256, 256>>>();
    k_hist<<<(EE + 255) / 256, 256>>>(ei);
    k_scan1<<<SCAN_BLOCKS, 512>>>();
    k_scan2<<<1, 256>>>(SCAN_BLOCKS);
    k_scan3<<<SCAN_BLOCKS, 512>>>();
    k_fill_csr<<<(EE + 255) / 256, 256>>>(ei);

    const int GB = (NN + 127) / 128;   // 782

    // input layer
    k_zero_stats<<<1, 128>>>();
    k_mma<<<GB, 256, GEMM_SMEM>>>(x, wt, (const __half*)0, (const float*)0, b_in, tmp, 1);
    k_bn_finalize<<<1, 128>>>(g_in, beta_in);
    k_bn_apply_relu<<<(NN * 32 + 255) / 256, 256>>>(tmp, h16);

    for (int i = 0; i < LLAYERS; i++) {
        k_agg<<<(NN * 32 + 255) / 256, 256>>>(h16, agg);
        int stats = (i < LLAYERS - 1) ? 1 : 0;
        if (stats) k_zero_stats<<<1, 128>>>();
        k_mma<<<GB, 256, GEMM_SMEM>>>(agg, wt + (1 + i) * HH * HH,
                                      h16, wt + (5 + i) * HH * HH,
                                      bl + i * HH, tmp, stats);
        if (stats) {
            k_bn_finalize<<<1, 128>>>(g_bn + i * HH, b_bn + i * HH);
            k_bn_apply_relu<<<(NN * 32 + 255) / 256, 256>>>(tmp, h16);
        }
    }

    k_mma_out<<<GB, 256, OUT_SMEM>>>(tmp, wt + 9 * HH * HH, b_out, out);
}

// round 9
// speedup vs baseline: 2.2194x; 1.3034x over previous
#include <cuda_runtime.h>
#include <cuda_bf16.h>
#include <cuda_fp16.h>
#include <cstdint>

#define NN 100000
#define EE 1600000
#define HH 128
#define CC 40
#define LLAYERS 4
#define BN_EPS 1e-5f

#define PITCH 136                      // 16-bit elements per smem row (128 + 8 pad)
#define PLANE (128 * PITCH)            // elements per 128-row plane

// ---------------- helpers ---------------------------------------------------
__device__ __forceinline__ uint32_t smem_u32(const void* p) {
    uint32_t a;
    asm("{ .reg .u64 t; cvta.to.shared.u64 t, %1; cvt.u32.u64 %0, t; }" : "=r"(a) : "l"(p));
    return a;
}

#define LDSM4(r0, r1, r2, r3, addr)                                             \
    asm volatile("ldmatrix.sync.aligned.m8n8.x4.shared.b16 {%0,%1,%2,%3}, [%4];" \
                 : "=r"(r0), "=r"(r1), "=r"(r2), "=r"(r3) : "r"(addr))

#define MMA_BF16(c, a0, a1, a2, a3, b0, b1)                                     \
    asm volatile("mma.sync.aligned.m16n8k16.row.col.f32.bf16.bf16.f32 "          \
                 "{%0,%1,%2,%3},{%4,%5,%6,%7},{%8,%9},{%0,%1,%2,%3};"            \
                 : "+f"((c)[0]), "+f"((c)[1]), "+f"((c)[2]), "+f"((c)[3])        \
                 : "r"(a0), "r"(a1), "r"(a2), "r"(a3), "r"(b0), "r"(b1))

#define MMA_F16(c, a0, a1, a2, a3, b0, b1)                                      \
    asm volatile("mma.sync.aligned.m16n8k16.row.col.f32.f16.f16.f32 "            \
                 "{%0,%1,%2,%3},{%4,%5,%6,%7},{%8,%9},{%0,%1,%2,%3};"            \
                 : "+f"((c)[0]), "+f"((c)[1]), "+f"((c)[2]), "+f"((c)[3])        \
                 : "r"(a0), "r"(a1), "r"(a2), "r"(a3), "r"(b0), "r"(b1))

// ---------------- scratch (device globals) ----------------------------------
__device__ __half g_h16[NN * HH];      // post-BN/ReLU activations (fp16)
__device__ __half g_agg16[NN * HH];    // aggregated means (fp16)
__device__ float g_tmp[NN * HH];
__device__ float g_wt[2 * HH * HH];    // fp32 W^T: slot0 = W_in, slot1 = W_out(padded)
__device__ __half g_wh[8 * HH * HH];   // fp16-hi W^T for Wl[0..3], Wr[0..3]
__device__ __half g_wl[8 * HH * HH];   // fp16-lo
__device__ int   g_deg[NN];
__device__ int   g_rowptr[NN + 1];
__device__ int   g_cursor[NN];
__device__ int   g_csrc[EE];
__device__ int   g_blocksum[256];
__device__ int   g_blockoff[256];
__device__ float g_sum[5][HH];
__device__ float g_sumsq[5][HH];
__device__ float g_scale[HH];
__device__ float g_shift[HH];

// ---------------- weight transpose + stat zero -------------------------------
// m=0: W_in->g_wt[0]; m=1..4: Wl->g_wh/g_wl[m-1]; m=5..8: Wr->g_wh/g_wl[m-1];
// m=9: W_out->g_wt[1]
__global__ void k_transpose(const float* __restrict__ W_in, const float* __restrict__ Wl,
                            const float* __restrict__ Wr, const float* __restrict__ W_out) {
    __shared__ float t[32][33];
    int m = blockIdx.z;
    const float* src;
    int stride, ncols;
    if (m == 0)      { src = W_in;                   stride = HH; ncols = HH; }
    else if (m <= 4) { src = Wl + (m - 1) * HH * HH; stride = HH; ncols = HH; }
    else if (m <= 8) { src = Wr + (m - 5) * HH * HH; stride = HH; ncols = HH; }
    else             { src = W_out;                  stride = CC; ncols = CC; }
    int bx = blockIdx.x * 32, by = blockIdx.y * 32;
    int tx = threadIdx.x;
    for (int i = threadIdx.y; i < 32; i += 8) {
        int c = bx + tx;
        t[i][tx] = (c < ncols) ? src[(by + i) * stride + c] : 0.f;
    }
    __syncthreads();
    for (int i = threadIdx.y; i < 32; i += 8) {
        float v = t[tx][i];
        int idx = (bx + i) * HH + by + tx;
        if (m == 0) {
            g_wt[idx] = v;
        } else if (m <= 8) {
            __half hi = __float2half_rn(v);
            __half lo = __float2half_rn(v - __half2float(hi));
            g_wh[(m - 1) * HH * HH + idx] = hi;
            g_wl[(m - 1) * HH * HH + idx] = lo;
        } else {
            g_wt[HH * HH + idx] = v;
        }
    }
    // zero stat slots (once per call)
    if (m == 0 && blockIdx.x == 0 && blockIdx.y == 0) {
        int c = threadIdx.y * 32 + tx;   // 0..255
        if (c < HH)
            for (int s = 0; s < 5; s++) { g_sum[s][c] = 0.f; g_sumsq[s][c] = 0.f; }
    }
}

// ---------------- CSR build --------------------------------------------------
__global__ void k_zero_deg() {
    int n = blockIdx.x * blockDim.x + threadIdx.x;
    if (n < NN) g_deg[n] = 0;
}
__global__ void k_hist(const int* __restrict__ ei) {
    int e = blockIdx.x * blockDim.x + threadIdx.x;
    if (e < EE) atomicAdd(&g_deg[ei[EE + e]], 1);
}
__global__ void k_scan1() {
    __shared__ int s[512];
    int tid = threadIdx.x;
    int n = blockIdx.x * 512 + tid;
    int v = (n < NN) ? g_deg[n] : 0;
    s[tid] = v;
    for (int off = 1; off < 512; off <<= 1) {
        __syncthreads();
        int t = (tid >= off) ? s[tid - off] : 0;
        __syncthreads();
        s[tid] += t;
    }
    if (n < NN) g_rowptr[n] = s[tid] - v;
    if (tid == 511) g_blocksum[blockIdx.x] = s[511];
}
__global__ void k_scan2(int nblocks) {
    __shared__ int s[256];
    int tid = threadIdx.x;
    int v = (tid < nblocks) ? g_blocksum[tid] : 0;
    s[tid] = v;
    for (int off = 1; off < 256; off <<= 1) {
        __syncthreads();
        int t = (tid >= off) ? s[tid - off] : 0;
        __syncthreads();
        s[tid] += t;
    }
    g_blockoff[tid] = s[tid] - v;
}
__global__ void k_scan3() {
    int tid = threadIdx.x;
    int n = blockIdx.x * 512 + tid;
    if (n < NN) {
        int r = g_rowptr[n] + g_blockoff[blockIdx.x];
        g_rowptr[n] = r;
        g_cursor[n] = r;
    }
    if (blockIdx.x == 0 && tid == 0) g_rowptr[NN] = EE;
}
__global__ void k_fill_csr(const int* __restrict__ ei) {
    int e = blockIdx.x * blockDim.x + threadIdx.x;
    if (e < EE) {
        int s = ei[e];
        int d = ei[EE + e];
        int pos = atomicAdd(&g_cursor[d], 1);
        g_csrc[pos] = s;
    }
}

// ---------------- neighbor mean aggregation (warp per node, fp16 in/out) ----
__global__ void k_agg(const __half* __restrict__ h, __half* __restrict__ agg) {
    int warp = (blockIdx.x * blockDim.x + threadIdx.x) >> 5;
    int lane = threadIdx.x & 31;
    if (warp >= NN) return;
    int beg = g_rowptr[warp];
    int end = g_rowptr[warp + 1];
    const uint2* hp = (const uint2*)h;
    float4 a0 = make_float4(0.f, 0.f, 0.f, 0.f);
    float4 a1 = make_float4(0.f, 0.f, 0.f, 0.f);
    int i = beg;
    for (; i + 1 < end; i += 2) {
        int s0 = g_csrc[i];
        int s1 = g_csrc[i + 1];
        uint2 u0 = hp[s0 * 32 + lane];
        uint2 u1 = hp[s1 * 32 + lane];
        float2 f00 = __half22float2(*(__half2*)&u0.x);
        float2 f01 = __half22float2(*(__half2*)&u0.y);
        float2 f10 = __half22float2(*(__half2*)&u1.x);
        float2 f11 = __half22float2(*(__half2*)&u1.y);
        a0.x += f00.x; a0.y += f00.y; a0.z += f01.x; a0.w += f01.y;
        a1.x += f10.x; a1.y += f10.y; a1.z += f11.x; a1.w += f11.y;
    }
    if (i < end) {
        int s0 = g_csrc[i];
        uint2 u0 = hp[s0 * 32 + lane];
        float2 f00 = __half22float2(*(__half2*)&u0.x);
        float2 f01 = __half22float2(*(__half2*)&u0.y);
        a0.x += f00.x; a0.y += f00.y; a0.z += f01.x; a0.w += f01.y;
    }
    int d = end - beg;
    float inv = 1.f / (float)(d > 0 ? d : 1);
    __half2 p0 = __floats2half2_rn((a0.x + a1.x) * inv, (a0.y + a1.y) * inv);
    __half2 p1 = __floats2half2_rn((a0.z + a1.z) * inv, (a0.w + a1.w) * inv);
    ((uint2*)agg)[warp * 32 + lane] = make_uint2(*(uint32_t*)&p0, *(uint32_t*)&p1);
}

// ---------------- fp16 fused layer GEMM -------------------------------------
// out[N,128] = A0@(B0hi+B0lo) + A1@(B1hi+B1lo) + bias ; optional BN stats
// smem planes (fp16): A0[0], A1[P], B0hi[2P], B0lo[3P], B1hi[4P], B1lo[5P]
__global__ __launch_bounds__(256, 1)
void k_mma_f16(const __half* __restrict__ A0, const __half* __restrict__ A1,
               const __half* __restrict__ B0hi, const __half* __restrict__ B0lo,
               const __half* __restrict__ B1hi, const __half* __restrict__ B1lo,
               const float* __restrict__ bias, float* __restrict__ out, int statsSlot) {
    extern __shared__ __half smh[];
    int tid = threadIdx.x, lane = tid & 31, wid = tid >> 5;
    int wm = wid & 3, wn = wid >> 2;
    int rowBase = blockIdx.x * 128;
    uint32_t smb = smem_u32(smh);

#pragma unroll
    for (int i = 0; i < 16; i++) {
        int f = tid + i * 256;
        int row = f >> 5, c4 = f & 31;
        int gr = rowBase + row;
        if (gr > NN - 1) gr = NN - 1;
        int goff = gr * HH + c4 * 4;
        int soff = row * PITCH + c4 * 4;
        *(uint2*)&smh[soff]         = *(const uint2*)&A0[goff];
        *(uint2*)&smh[PLANE + soff] = *(const uint2*)&A1[goff];
    }
#pragma unroll
    for (int i = 0; i < 16; i++) {
        int f = tid + i * 256;
        int row = f >> 5, c4 = f & 31;
        int goff = row * HH + c4 * 4;
        int soff = row * PITCH + c4 * 4;
        *(uint2*)&smh[2 * PLANE + soff] = *(const uint2*)&B0hi[goff];
        *(uint2*)&smh[3 * PLANE + soff] = *(const uint2*)&B0lo[goff];
        *(uint2*)&smh[4 * PLANE + soff] = *(const uint2*)&B1hi[goff];
        *(uint2*)&smh[5 * PLANE + soff] = *(const uint2*)&B1lo[goff];
    }
    __syncthreads();

    float acc[2][8][4];
#pragma unroll
    for (int mt = 0; mt < 2; mt++)
#pragma unroll
        for (int nt = 0; nt < 8; nt++)
#pragma unroll
            for (int c = 0; c < 4; c++) acc[mt][nt][c] = 0.f;

    int arow = wm * 32 + (lane & 15);
    int brow = wn * 64 + (lane & 15);
    int coff = (lane >> 4) * 8;

#pragma unroll
    for (int s = 0; s < 2; s++) {
        uint32_t ap = smb + (uint32_t)(s * PLANE * 2);
        uint32_t bp = smb + (uint32_t)((2 + 2 * s) * PLANE * 2);
#pragma unroll 2
        for (int ks = 0; ks < 8; ks++) {
            int col = ks * 16 + coff;
            uint32_t ah[2][4], bh[4][4], bl[4][4];
#pragma unroll
            for (int mt = 0; mt < 2; mt++) {
                uint32_t a = ap + (uint32_t)(((arow + mt * 16) * PITCH + col) * 2);
                LDSM4(ah[mt][0], ah[mt][1], ah[mt][2], ah[mt][3], a);
            }
#pragma unroll
            for (int n2 = 0; n2 < 4; n2++) {
                uint32_t b = bp + (uint32_t)(((brow + n2 * 16) * PITCH + col) * 2);
                LDSM4(bh[n2][0], bh[n2][1], bh[n2][2], bh[n2][3], b);
                LDSM4(bl[n2][0], bl[n2][1], bl[n2][2], bl[n2][3], b + PLANE * 2);
            }
#pragma unroll
            for (int mt = 0; mt < 2; mt++)
#pragma unroll
                for (int nt = 0; nt < 8; nt++) {
                    int n2 = nt >> 1, w = nt & 1;
                    MMA_F16(acc[mt][nt], ah[mt][0], ah[mt][1], ah[mt][2], ah[mt][3],
                            bh[n2][w], bh[n2][w + 2]);
                    MMA_F16(acc[mt][nt], ah[mt][0], ah[mt][1], ah[mt][2], ah[mt][3],
                            bl[n2][w], bl[n2][w + 2]);
                }
        }
    }

    // epilogue + fused BN stats
    float cs[8][2], cq[8][2];
#pragma unroll
    for (int nt = 0; nt < 8; nt++) { cs[nt][0] = cs[nt][1] = cq[nt][0] = cq[nt][1] = 0.f; }

#pragma unroll
    for (int mt = 0; mt < 2; mt++) {
        int r0 = rowBase + wm * 32 + mt * 16 + (lane >> 2);
#pragma unroll
        for (int nt = 0; nt < 8; nt++) {
            int col = wn * 64 + nt * 8 + (lane & 3) * 2;
            float b0 = bias[col], b1 = bias[col + 1];
            float v0 = acc[mt][nt][0] + b0, v1 = acc[mt][nt][1] + b1;
            float v2 = acc[mt][nt][2] + b0, v3 = acc[mt][nt][3] + b1;
            if (r0 < NN) {
                *(float2*)&out[r0 * HH + col] = make_float2(v0, v1);
                cs[nt][0] += v0; cs[nt][1] += v1;
                cq[nt][0] += v0 * v0; cq[nt][1] += v1 * v1;
            }
            if (r0 + 8 < NN) {
                *(float2*)&out[(r0 + 8) * HH + col] = make_float2(v2, v3);
                cs[nt][0] += v2; cs[nt][1] += v3;
                cq[nt][0] += v2 * v2; cq[nt][1] += v3 * v3;
            }
        }
    }
    if (statsSlot >= 0) {
#pragma unroll
        for (int nt = 0; nt < 8; nt++)
#pragma unroll
            for (int j = 0; j < 2; j++) {
                float sv = cs[nt][j], qv = cq[nt][j];
                sv += __shfl_xor_sync(0xFFFFFFFFu, sv, 4);
                sv += __shfl_xor_sync(0xFFFFFFFFu, sv, 8);
                sv += __shfl_xor_sync(0xFFFFFFFFu, sv, 16);
                qv += __shfl_xor_sync(0xFFFFFFFFu, qv, 4);
                qv += __shfl_xor_sync(0xFFFFFFFFu, qv, 8);
                qv += __shfl_xor_sync(0xFFFFFFFFu, qv, 16);
                if (lane < 4) {
                    int col = wn * 64 + nt * 8 + lane * 2 + j;
                    atomicAdd(&g_sum[statsSlot][col], sv);
                    atomicAdd(&g_sumsq[statsSlot][col], qv);
                }
            }
    }
}

// ---------------- split-bf16 conversion + smem store (fp32 sources) ---------
__device__ __forceinline__ void cvt_store4(__nv_bfloat16* smbase, int idx, float4 v) {
    __nv_bfloat16 h0 = __float2bfloat16_rn(v.x);
    __nv_bfloat16 h1 = __float2bfloat16_rn(v.y);
    __nv_bfloat16 h2 = __float2bfloat16_rn(v.z);
    __nv_bfloat16 h3 = __float2bfloat16_rn(v.w);
    __nv_bfloat16 l0 = __float2bfloat16_rn(v.x - __bfloat162float(h0));
    __nv_bfloat16 l1 = __float2bfloat16_rn(v.y - __bfloat162float(h1));
    __nv_bfloat16 l2 = __float2bfloat16_rn(v.z - __bfloat162float(h2));
    __nv_bfloat16 l3 = __float2bfloat16_rn(v.w - __bfloat162float(h3));
    uint32_t p01 = (uint32_t)__bfloat16_as_ushort(h0) | ((uint32_t)__bfloat16_as_ushort(h1) << 16);
    uint32_t p23 = (uint32_t)__bfloat16_as_ushort(h2) | ((uint32_t)__bfloat16_as_ushort(h3) << 16);
    uint32_t q01 = (uint32_t)__bfloat16_as_ushort(l0) | ((uint32_t)__bfloat16_as_ushort(l1) << 16);
    uint32_t q23 = (uint32_t)__bfloat16_as_ushort(l2) | ((uint32_t)__bfloat16_as_ushort(l3) << 16);
    *(uint2*)(smbase + idx)         = make_uint2(p01, p23);
    *(uint2*)(smbase + PLANE + idx) = make_uint2(q01, q23);
}

// ---------------- bf16-3-term GEMM (fp32 A,B) — input layer -----------------
__global__ __launch_bounds__(256, 1)
void k_mma32(const float* __restrict__ A0, const float* __restrict__ B0t,
             const float* __restrict__ bias, float* __restrict__ out, int statsSlot) {
    extern __shared__ __nv_bfloat16 sm[];
    int tid = threadIdx.x, lane = tid & 31, wid = tid >> 5;
    int wm = wid & 3, wn = wid >> 2;
    int rowBase = blockIdx.x * 128;
    uint32_t smb = smem_u32(sm);

    float acc[2][8][4];
#pragma unroll
    for (int mt = 0; mt < 2; mt++)
#pragma unroll
        for (int nt = 0; nt < 8; nt++)
#pragma unroll
            for (int c = 0; c < 4; c++) acc[mt][nt][c] = 0.f;

#pragma unroll
    for (int i = 0; i < 16; i++) {
        int f = tid + i * 256;
        int row = f >> 5, c4 = f & 31;
        int gr = rowBase + row;
        if (gr > NN - 1) gr = NN - 1;
        float4 v = *(const float4*)&A0[gr * HH + c4 * 4];
        cvt_store4(sm, row * PITCH + c4 * 4, v);
    }
#pragma unroll
    for (int i = 0; i < 16; i++) {
        int f = tid + i * 256;
        int row = f >> 5, c4 = f & 31;
        float4 v = *(const float4*)&B0t[row * HH + c4 * 4];
        cvt_store4(sm + 2 * PLANE, row * PITCH + c4 * 4, v);
    }
    __syncthreads();

    int arow = wm * 32 + (lane & 15);
    int brow = wn * 64 + (lane & 15);
    int coff = (lane >> 4) * 8;
#pragma unroll 2
    for (int ks = 0; ks < 8; ks++) {
        int col = ks * 16 + coff;
        uint32_t ah[2][4], al[2][4], bh[4][4], bl[4][4];
#pragma unroll
        for (int mt = 0; mt < 2; mt++) {
            uint32_t a = smb + (uint32_t)(((arow + mt * 16) * PITCH + col) * 2);
            LDSM4(ah[mt][0], ah[mt][1], ah[mt][2], ah[mt][3], a);
            LDSM4(al[mt][0], al[mt][1], al[mt][2], al[mt][3], a + PLANE * 2);
        }
#pragma unroll
        for (int n2 = 0; n2 < 4; n2++) {
            uint32_t b = smb + (uint32_t)((2 * PLANE + (brow + n2 * 16) * PITCH + col) * 2);
            LDSM4(bh[n2][0], bh[n2][1], bh[n2][2], bh[n2][3], b);
            LDSM4(bl[n2][0], bl[n2][1], bl[n2][2], bl[n2][3], b + PLANE * 2);
        }
#pragma unroll
        for (int mt = 0; mt < 2; mt++)
#pragma unroll
            for (int nt = 0; nt < 8; nt++) {
                int n2 = nt >> 1, w = nt & 1;
                MMA_BF16(acc[mt][nt], ah[mt][0], ah[mt][1], ah[mt][2], ah[mt][3],
                         bh[n2][w], bh[n2][w + 2]);
                MMA_BF16(acc[mt][nt], ah[mt][0], ah[mt][1], ah[mt][2], ah[mt][3],
                         bl[n2][w], bl[n2][w + 2]);
                MMA_BF16(acc[mt][nt], al[mt][0], al[mt][1], al[mt][2], al[mt][3],
                         bh[n2][w], bh[n2][w + 2]);
            }
    }

    float cs[8][2], cq[8][2];
#pragma unroll
    for (int nt = 0; nt < 8; nt++) { cs[nt][0] = cs[nt][1] = cq[nt][0] = cq[nt][1] = 0.f; }
#pragma unroll
    for (int mt = 0; mt < 2; mt++) {
        int r0 = rowBase + wm * 32 + mt * 16 + (lane >> 2);
#pragma unroll
        for (int nt = 0; nt < 8; nt++) {
            int col = wn * 64 + nt * 8 + (lane & 3) * 2;
            float b0 = bias[col], b1 = bias[col + 1];
            float v0 = acc[mt][nt][0] + b0, v1 = acc[mt][nt][1] + b1;
            float v2 = acc[mt][nt][2] + b0, v3 = acc[mt][nt][3] + b1;
            if (r0 < NN) {
                *(float2*)&out[r0 * HH + col] = make_float2(v0, v1);
                cs[nt][0] += v0; cs[nt][1] += v1;
                cq[nt][0] += v0 * v0; cq[nt][1] += v1 * v1;
            }
            if (r0 + 8 < NN) {
                *(float2*)&out[(r0 + 8) * HH + col] = make_float2(v2, v3);
                cs[nt][0] += v2; cs[nt][1] += v3;
                cq[nt][0] += v2 * v2; cq[nt][1] += v3 * v3;
            }
        }
    }
#pragma unroll
    for (int nt = 0; nt < 8; nt++)
#pragma unroll
        for (int j = 0; j < 2; j++) {
            float sv = cs[nt][j], qv = cq[nt][j];
            sv += __shfl_xor_sync(0xFFFFFFFFu, sv, 4);
            sv += __shfl_xor_sync(0xFFFFFFFFu, sv, 8);
            sv += __shfl_xor_sync(0xFFFFFFFFu, sv, 16);
            qv += __shfl_xor_sync(0xFFFFFFFFu, qv, 4);
            qv += __shfl_xor_sync(0xFFFFFFFFu, qv, 8);
            qv += __shfl_xor_sync(0xFFFFFFFFu, qv, 16);
            if (lane < 4) {
                int col = wn * 64 + nt * 8 + lane * 2 + j;
                atomicAdd(&g_sum[statsSlot][col], sv);
                atomicAdd(&g_sumsq[statsSlot][col], qv);
            }
        }
}

// ---------------- tensor output GEMM: out[N,40] = A@Bt + b ------------------
__global__ __launch_bounds__(256, 1)
void k_mma_out(const float* __restrict__ A, const float* __restrict__ Bt,
               const float* __restrict__ bias, float* __restrict__ out) {
    extern __shared__ __nv_bfloat16 sm[];
    const int BPL = 64 * PITCH;
    int tid = threadIdx.x, lane = tid & 31, wid = tid >> 5;
    int wm = wid & 3, wn = wid >> 2;
    int rowBase = blockIdx.x * 128;
    uint32_t smb = smem_u32(sm);

    float acc[2][4][4];
#pragma unroll
    for (int mt = 0; mt < 2; mt++)
#pragma unroll
        for (int nt = 0; nt < 4; nt++)
#pragma unroll
            for (int c = 0; c < 4; c++) acc[mt][nt][c] = 0.f;

#pragma unroll
    for (int i = 0; i < 16; i++) {
        int f = tid + i * 256;
        int row = f >> 5, c4 = f & 31;
        int gr = rowBase + row;
        if (gr > NN - 1) gr = NN - 1;
        float4 v = *(const float4*)&A[gr * HH + c4 * 4];
        cvt_store4(sm, row * PITCH + c4 * 4, v);
    }
#pragma unroll
    for (int i = 0; i < 8; i++) {
        int f = tid + i * 256;
        int row = f >> 5, c4 = f & 31;
        float4 v = *(const float4*)&Bt[row * HH + c4 * 4];
        __nv_bfloat16 h0 = __float2bfloat16_rn(v.x), h1 = __float2bfloat16_rn(v.y);
        __nv_bfloat16 h2 = __float2bfloat16_rn(v.z), h3 = __float2bfloat16_rn(v.w);
        __nv_bfloat16 l0 = __float2bfloat16_rn(v.x - __bfloat162float(h0));
        __nv_bfloat16 l1 = __float2bfloat16_rn(v.y - __bfloat162float(h1));
        __nv_bfloat16 l2 = __float2bfloat16_rn(v.z - __bfloat162float(h2));
        __nv_bfloat16 l3 = __float2bfloat16_rn(v.w - __bfloat162float(h3));
        uint32_t p01 = (uint32_t)__bfloat16_as_ushort(h0) | ((uint32_t)__bfloat16_as_ushort(h1) << 16);
        uint32_t p23 = (uint32_t)__bfloat16_as_ushort(h2) | ((uint32_t)__bfloat16_as_ushort(h3) << 16);
        uint32_t q01 = (uint32_t)__bfloat16_as_ushort(l0) | ((uint32_t)__bfloat16_as_ushort(l1) << 16);
        uint32_t q23 = (uint32_t)__bfloat16_as_ushort(l2) | ((uint32_t)__bfloat16_as_ushort(l3) << 16);
        int idx = 2 * PLANE + row * PITCH + c4 * 4;
        *(uint2*)(sm + idx)       = make_uint2(p01, p23);
        *(uint2*)(sm + idx + BPL) = make_uint2(q01, q23);
    }
    __syncthreads();

    int arow = wm * 32 + (lane & 15);
    int brow = wn * 32 + (lane & 15);
    int coff = (lane >> 4) * 8;
#pragma unroll 2
    for (int ks = 0; ks < 8; ks++) {
        int col = ks * 16 + coff;
        uint32_t ah[2][4], al[2][4], bh[2][4], bl[2][4];
#pragma unroll
        for (int mt = 0; mt < 2; mt++) {
            uint32_t a = smb + (uint32_t)(((arow + mt * 16) * PITCH + col) * 2);
            LDSM4(ah[mt][0], ah[mt][1], ah[mt][2], ah[mt][3], a);
            LDSM4(al[mt][0], al[mt][1], al[mt][2], al[mt][3], a + PLANE * 2);
        }
#pragma unroll
        for (int n2 = 0; n2 < 2; n2++) {
            uint32_t b = smb + (uint32_t)((2 * PLANE + (brow + n2 * 16) * PITCH + col) * 2);
            LDSM4(bh[n2][0], bh[n2][1], bh[n2][2], bh[n2][3], b);
            LDSM4(bl[n2][0], bl[n2][1], bl[n2][2], bl[n2][3], b + BPL * 2);
        }
#pragma unroll
        for (int mt = 0; mt < 2; mt++)
#pragma unroll
            for (int nt = 0; nt < 4; nt++) {
                int n2 = nt >> 1, w = nt & 1;
                MMA_BF16(acc[mt][nt], ah[mt][0], ah[mt][1], ah[mt][2], ah[mt][3],
                         bh[n2][w], bh[n2][w + 2]);
                MMA_BF16(acc[mt][nt], ah[mt][0], ah[mt][1], ah[mt][2], ah[mt][3],
                         bl[n2][w], bl[n2][w + 2]);
                MMA_BF16(acc[mt][nt], al[mt][0], al[mt][1], al[mt][2], al[mt][3],
                         bh[n2][w], bh[n2][w + 2]);
            }
    }

#pragma unroll
    for (int mt = 0; mt < 2; mt++) {
        int r0 = rowBase + wm * 32 + mt * 16 + (lane >> 2);
#pragma unroll
        for (int nt = 0; nt < 4; nt++) {
            int col = wn * 32 + nt * 8 + (lane & 3) * 2;
            if (col < CC) {
                float b0 = bias[col], b1 = bias[col + 1];
                if (r0 < NN)
                    *(float2*)&out[r0 * CC + col] =
                        make_float2(acc[mt][nt][0] + b0, acc[mt][nt][1] + b1);
                if (r0 + 8 < NN)
                    *(float2*)&out[(r0 + 8) * CC + col] =
                        make_float2(acc[mt][nt][2] + b0, acc[mt][nt][3] + b1);
            }
        }
    }
}

// ---------------- BatchNorm -------------------------------------------------
__global__ void k_bn_finalize(const float* __restrict__ g, const float* __restrict__ beta,
                              int slot) {
    int c = threadIdx.x;
    if (c < HH) {
        float mean = g_sum[slot][c] * (1.f / NN);
        float var = g_sumsq[slot][c] * (1.f / NN) - mean * mean;
        float sc = g[c] * rsqrtf(var + BN_EPS);
        g_scale[c] = sc;
        g_shift[c] = beta[c] - mean * sc;
    }
}
__global__ void k_bn_apply_relu(const float* __restrict__ t, __half* __restrict__ h) {
    int idx = blockIdx.x * blockDim.x + threadIdx.x;
    if (idx >= NN * 32) return;
    int c4 = idx & 31;
    float4 v = ((const float4*)t)[idx];
    float4 sc = *(const float4*)&g_scale[c4 * 4];
    float4 sh = *(const float4*)&g_shift[c4 * 4];
    float r0 = fmaxf(v.x * sc.x + sh.x, 0.f);
    float r1 = fmaxf(v.y * sc.y + sh.y, 0.f);
    float r2 = fmaxf(v.z * sc.z + sh.z, 0.f);
    float r3 = fmaxf(v.w * sc.w + sh.w, 0.f);
    __half2 p0 = __floats2half2_rn(r0, r1);
    __half2 p1 = __floats2half2_rn(r2, r3);
    ((uint2*)h)[idx] = make_uint2(*(uint32_t*)&p0, *(uint32_t*)&p1);
}

// ---------------- host orchestration ----------------------------------------
extern "C" void kernel_launch(void* const* d_in, const int* in_sizes, int n_in,
                              void* d_out, int out_size) {
    const float* x       = (const float*)d_in[0];
    const float* W_in    = (const float*)d_in[1];
    const float* b_in    = (const float*)d_in[2];
    const float* g_in    = (const float*)d_in[3];
    const float* beta_in = (const float*)d_in[4];
    const float* Wl      = (const float*)d_in[5];
    const float* bl      = (const float*)d_in[6];
    const float* Wr      = (const float*)d_in[7];
    const float* g_bn    = (const float*)d_in[8];
    const float* b_bn    = (const float*)d_in[9];
    const float* W_out   = (const float*)d_in[10];
    const float* b_out   = (const float*)d_in[11];
    const int*   ei      = (const int*)d_in[12];
    float* out = (float*)d_out;

    void* p;
    cudaGetSymbolAddress(&p, g_h16);   __half* h16   = (__half*)p;
    cudaGetSymbolAddress(&p, g_agg16); __half* agg16 = (__half*)p;
    cudaGetSymbolAddress(&p, g_tmp);   float* tmp    = (float*)p;
    cudaGetSymbolAddress(&p, g_wt);    float* wt     = (float*)p;
    cudaGetSymbolAddress(&p, g_wh);    __half* wh    = (__half*)p;
    cudaGetSymbolAddress(&p, g_wl);    __half* wl    = (__half*)p;

    const int F16_SMEM  = 6 * PLANE * 2;                       // 208896 B
    const int B32_SMEM  = 4 * PLANE * 2;                       // 139264 B
    const int OUT_SMEM  = (2 * PLANE + 2 * 64 * PITCH) * 2;    // 104448 B
    cudaFuncSetAttribute(k_mma_f16, cudaFuncAttributeMaxDynamicSharedMemorySize, F16_SMEM);
    cudaFuncSetAttribute(k_mma32, cudaFuncAttributeMaxDynamicSharedMemorySize, B32_SMEM);
    cudaFuncSetAttribute(k_mma_out, cudaFuncAttributeMaxDynamicSharedMemorySize, OUT_SMEM);

    const int SCAN_BLOCKS = (NN + 511) / 512;

    k_transpose<<<dim3(4, 4, 10), dim3(32, 8)>>>(W_in, Wl, Wr, W_out);

    k_zero_deg<<<(NN + 255) / 256, 256>>>();
    k_hist<<<(EE + 255) / 256, 256>>>(ei);
    k_scan1<<<SCAN_BLOCKS, 512>>>();
    k_scan2<<<1, 256>>>(SCAN_BLOCKS);
    k_scan3<<<SCAN_BLOCKS, 512>>>();
    k_fill_csr<<<(EE + 255) / 256, 256>>>(ei);

    const int GB = (NN + 127) / 128;   // 782

    // input layer: bf16-3-term exact path, stats slot 0
    k_mma32<<<GB, 256, B32_SMEM>>>(x, wt, b_in, tmp, 0);
    k_bn_finalize<<<1, 128>>>(g_in, beta_in, 0);
    k_bn_apply_relu<<<(NN * 32 + 255) / 256, 256>>>(tmp, h16);

    for (int i = 0; i < LLAYERS; i++) {
        k_agg<<<(NN * 32 + 255) / 256, 256>>>(h16, agg16);
        int slot = (i < LLAYERS - 1) ? (1 + i) : -1;
        k_mma_f16<<<GB, 256, F16_SMEM>>>(agg16, h16,
                                         wh + i * HH * HH,       wl + i * HH * HH,
                                         wh + (4 + i) * HH * HH, wl + (4 + i) * HH * HH,
                                         bl + i * HH, tmp, slot);
        if (slot >= 0) {
            k_bn_finalize<<<1, 128>>>(g_bn + i * HH, b_bn + i * HH, slot);
            k_bn_apply_relu<<<(NN * 32 + 255) / 256, 256>>>(tmp, h16);
        }
    }

    k_mma_out<<<GB, 256, OUT_SMEM>>>(tmp, wt + HH * HH, b_out, out);
}